// round 1
// baseline (speedup 1.0000x reference)
#include <cuda_runtime.h>
#include <math.h>

#define N_EMBD   1024
#define N_HEAD   16
#define HEAD_DIM 64
#define BATCH    4
#define SEQ      2048
#define M_TOT    (BATCH * SEQ)   // 8192 tokens

// Scratch: __device__ globals (no runtime allocation allowed).
__device__ float g_Q[(size_t)BATCH * N_HEAD * SEQ * HEAD_DIM]; // (B,H,T,D)
__device__ float g_K[(size_t)BATCH * N_HEAD * SEQ * HEAD_DIM];
__device__ float g_V[(size_t)BATCH * N_HEAD * SEQ * HEAD_DIM];
__device__ float g_O[(size_t)BATCH * SEQ * N_EMBD];            // (B,T,C)

// ---------------------------------------------------------------------------
// GEMM tiles: 128x128 block, K-step 8, 256 threads, 8x8 per-thread microtile.
// ---------------------------------------------------------------------------
#define BM 128
#define BN 128
#define BK 8
#define TM 8
#define TN 8

// QKV projection: out[m][n] = x[m][:] . W[:][n] + b[n], written permuted to
// (B,H,T,D). blockIdx.z selects which of Q/K/V.
__global__ __launch_bounds__(256) void qkv_gemm_kernel(
    const float* __restrict__ X,
    const float* __restrict__ Wq, const float* __restrict__ bq,
    const float* __restrict__ Wk, const float* __restrict__ bk,
    const float* __restrict__ Wv, const float* __restrict__ bv)
{
    const int K = N_EMBD, N = N_EMBD;
    const int z = blockIdx.z;
    const float* W    = (z == 0) ? Wq : ((z == 1) ? Wk : Wv);
    const float* bias = (z == 0) ? bq : ((z == 1) ? bk : bv);
    float* out        = (z == 0) ? g_Q : ((z == 1) ? g_K : g_V);

    __shared__ float As[BK][BM];
    __shared__ float Bs[BK][BN];

    const int tid = threadIdx.x;
    const int tr = (tid / 16) * TM;
    const int tc = (tid % 16) * TN;
    const int m0 = blockIdx.y * BM;
    const int n0 = blockIdx.x * BN;

    const int aRow = tid >> 1;
    const int aCol = (tid & 1) * 4;
    const int bRow = tid >> 5;
    const int bCol = (tid & 31) * 4;

    const float* Ag = X + (size_t)m0 * K;
    const float* Bg = W + n0;

    float acc[TM][TN];
#pragma unroll
    for (int i = 0; i < TM; i++)
#pragma unroll
        for (int j = 0; j < TN; j++) acc[i][j] = 0.f;

    for (int k0 = 0; k0 < K; k0 += BK) {
        float4 av = *(const float4*)(Ag + (size_t)aRow * K + k0 + aCol);
        As[aCol + 0][aRow] = av.x;
        As[aCol + 1][aRow] = av.y;
        As[aCol + 2][aRow] = av.z;
        As[aCol + 3][aRow] = av.w;
        *(float4*)&Bs[bRow][bCol] =
            *(const float4*)(Bg + (size_t)(k0 + bRow) * N + bCol);
        __syncthreads();
#pragma unroll
        for (int kk = 0; kk < BK; kk++) {
            float4 a0 = *(float4*)&As[kk][tr];
            float4 a1 = *(float4*)&As[kk][tr + 4];
            float4 b0 = *(float4*)&Bs[kk][tc];
            float4 b1 = *(float4*)&Bs[kk][tc + 4];
            float ar[8] = {a0.x, a0.y, a0.z, a0.w, a1.x, a1.y, a1.z, a1.w};
            float br[8] = {b0.x, b0.y, b0.z, b0.w, b1.x, b1.y, b1.z, b1.w};
#pragma unroll
            for (int i = 0; i < 8; i++)
#pragma unroll
                for (int j = 0; j < 8; j++) acc[i][j] += ar[i] * br[j];
        }
        __syncthreads();
    }

    // Write permuted to (B,H,T,D).
#pragma unroll
    for (int i = 0; i < TM; i++) {
        int m = m0 + tr + i;
        int b = m >> 11;          // / SEQ
        int t = m & (SEQ - 1);
#pragma unroll
        for (int j = 0; j < TN; j++) {
            int n = n0 + tc + j;
            int h = n >> 6;       // / HEAD_DIM
            int d = n & 63;
            out[(((size_t)(b * N_HEAD + h)) * SEQ + t) * HEAD_DIM + d] =
                acc[i][j] + bias[n];
        }
    }
}

// Output projection: d_out = g_O @ Wp + bp, plain row-major (B*T, C).
__global__ __launch_bounds__(256) void proj_gemm_kernel(
    const float* __restrict__ Wp, const float* __restrict__ bp,
    float* __restrict__ out)
{
    const int K = N_EMBD, N = N_EMBD;
    const float* X = g_O;

    __shared__ float As[BK][BM];
    __shared__ float Bs[BK][BN];

    const int tid = threadIdx.x;
    const int tr = (tid / 16) * TM;
    const int tc = (tid % 16) * TN;
    const int m0 = blockIdx.y * BM;
    const int n0 = blockIdx.x * BN;

    const int aRow = tid >> 1;
    const int aCol = (tid & 1) * 4;
    const int bRow = tid >> 5;
    const int bCol = (tid & 31) * 4;

    const float* Ag = X + (size_t)m0 * K;
    const float* Bg = Wp + n0;

    float acc[TM][TN];
#pragma unroll
    for (int i = 0; i < TM; i++)
#pragma unroll
        for (int j = 0; j < TN; j++) acc[i][j] = 0.f;

    for (int k0 = 0; k0 < K; k0 += BK) {
        float4 av = *(const float4*)(Ag + (size_t)aRow * K + k0 + aCol);
        As[aCol + 0][aRow] = av.x;
        As[aCol + 1][aRow] = av.y;
        As[aCol + 2][aRow] = av.z;
        As[aCol + 3][aRow] = av.w;
        *(float4*)&Bs[bRow][bCol] =
            *(const float4*)(Bg + (size_t)(k0 + bRow) * N + bCol);
        __syncthreads();
#pragma unroll
        for (int kk = 0; kk < BK; kk++) {
            float4 a0 = *(float4*)&As[kk][tr];
            float4 a1 = *(float4*)&As[kk][tr + 4];
            float4 b0 = *(float4*)&Bs[kk][tc];
            float4 b1 = *(float4*)&Bs[kk][tc + 4];
            float ar[8] = {a0.x, a0.y, a0.z, a0.w, a1.x, a1.y, a1.z, a1.w};
            float br[8] = {b0.x, b0.y, b0.z, b0.w, b1.x, b1.y, b1.z, b1.w};
#pragma unroll
            for (int i = 0; i < 8; i++)
#pragma unroll
                for (int j = 0; j < 8; j++) acc[i][j] += ar[i] * br[j];
        }
        __syncthreads();
    }

#pragma unroll
    for (int i = 0; i < TM; i++) {
        int m = m0 + tr + i;
#pragma unroll
        for (int j = 0; j < TN; j += 4) {
            int n = n0 + tc + j;
            float4 v = make_float4(acc[i][j] + bp[n], acc[i][j + 1] + bp[n + 1],
                                   acc[i][j + 2] + bp[n + 2],
                                   acc[i][j + 3] + bp[n + 3]);
            *(float4*)&out[(size_t)m * N + n] = v;
        }
    }
}

// ---------------------------------------------------------------------------
// Fused causal attention (flash-style, fp32).
// Block: one (b, h, 64-query tile). 256 threads; thread microtile 4 rows x 4
// cols. Smem tiles stored transposed (stride 68) so both operands of the
// score/PV inner loops are contiguous float4 LDS.
// ---------------------------------------------------------------------------
#define APAD 68
#define ATTN_SMEM (4 * 64 * APAD * 4)  // 69632 bytes

__global__ __launch_bounds__(256) void attn_kernel()
{
    extern __shared__ float sm[];
    float* QsT = sm;                 // [k][r]  64 x APAD
    float* KsT = sm + 64 * APAD;     // [k][c]
    float* Vs  = sm + 2 * 64 * APAD; // [s][d]
    float* PsT = sm + 3 * 64 * APAD; // [s][r]

    const int qb = blockIdx.x;   // query tile (0..31)
    const int h  = blockIdx.y;
    const int b  = blockIdx.z;
    const int tid = threadIdx.x;
    const int tr = (tid >> 4) << 2;  // row group: 4 rows
    const int tc = (tid & 15) << 2;  // col group: 4 cols

    const float* Qg = g_Q + (((size_t)(b * N_HEAD + h)) * SEQ + qb * 64) * 64;
    const float* Kbase = g_K + ((size_t)(b * N_HEAD + h)) * SEQ * 64;
    const float* Vbase = g_V + ((size_t)(b * N_HEAD + h)) * SEQ * 64;

    // Load Q tile transposed: QsT[k][r] = Q[r][k]
    for (int idx = tid; idx < 64 * 64; idx += 256) {
        int r = idx >> 6, k = idx & 63;
        QsT[k * APAD + r] = Qg[idx];
    }

    float o[4][4];
    float m_i[4], l_i[4];
#pragma unroll
    for (int i = 0; i < 4; i++) {
        m_i[i] = -1e30f;
        l_i[i] = 0.f;
#pragma unroll
        for (int j = 0; j < 4; j++) o[i][j] = 0.f;
    }

    __syncthreads();

    for (int kb = 0; kb <= qb; kb++) {
        const float* Kg = Kbase + (size_t)kb * 64 * 64;
        const float* Vg = Vbase + (size_t)kb * 64 * 64;
        // K transposed; V natural layout (vectorized copy).
        for (int idx = tid; idx < 64 * 64; idx += 256) {
            int c = idx >> 6, k = idx & 63;
            KsT[k * APAD + c] = Kg[idx];
        }
        for (int idx = tid; idx < 64 * 16; idx += 256) {
            int r = idx >> 4, c4 = (idx & 15) << 2;
            *(float4*)&Vs[r * APAD + c4] = *(const float4*)&Vg[r * 64 + c4];
        }
        __syncthreads();

        // S = Q K^T (4x4 microtile), scale 1/sqrt(64)
        float s[4][4];
#pragma unroll
        for (int i = 0; i < 4; i++)
#pragma unroll
            for (int j = 0; j < 4; j++) s[i][j] = 0.f;

#pragma unroll 4
        for (int k = 0; k < 64; k++) {
            float4 a  = *(float4*)&QsT[k * APAD + tr];
            float4 bb = *(float4*)&KsT[k * APAD + tc];
            float ar[4] = {a.x, a.y, a.z, a.w};
            float br[4] = {bb.x, bb.y, bb.z, bb.w};
#pragma unroll
            for (int i = 0; i < 4; i++)
#pragma unroll
                for (int j = 0; j < 4; j++) s[i][j] += ar[i] * br[j];
        }

        const bool diag = (kb == qb);
#pragma unroll
        for (int i = 0; i < 4; i++)
#pragma unroll
            for (int j = 0; j < 4; j++) {
                s[i][j] *= 0.125f;  // 1/sqrt(64)
                if (diag && (tc + j > tr + i)) s[i][j] = -1e30f;
            }

        // Online softmax update. Row r = tr+i is owned by the 16 threads with
        // the same tid>>4 (consecutive lanes -> shfl group of 16).
#pragma unroll
        for (int i = 0; i < 4; i++) {
            float tmax = fmaxf(fmaxf(s[i][0], s[i][1]), fmaxf(s[i][2], s[i][3]));
#pragma unroll
            for (int off = 1; off < 16; off <<= 1)
                tmax = fmaxf(tmax, __shfl_xor_sync(0xffffffffu, tmax, off));
            float m_new = fmaxf(m_i[i], tmax);
            float scale = __expf(m_i[i] - m_new);
            float rsum = 0.f;
#pragma unroll
            for (int j = 0; j < 4; j++) {
                float p = __expf(s[i][j] - m_new);
                s[i][j] = p;  // reuse as P
                rsum += p;
            }
#pragma unroll
            for (int off = 1; off < 16; off <<= 1)
                rsum += __shfl_xor_sync(0xffffffffu, rsum, off);
            l_i[i] = l_i[i] * scale + rsum;
            m_i[i] = m_new;
#pragma unroll
            for (int j = 0; j < 4; j++) o[i][j] *= scale;
        }

        // Publish P transposed: PsT[s][r]
#pragma unroll
        for (int i = 0; i < 4; i++)
#pragma unroll
            for (int j = 0; j < 4; j++)
                PsT[(tc + j) * APAD + tr + i] = s[i][j];
        __syncthreads();

        // O += P @ V
#pragma unroll 4
        for (int ks = 0; ks < 64; ks++) {
            float4 pr = *(float4*)&PsT[ks * APAD + tr];
            float4 vr = *(float4*)&Vs[ks * APAD + tc];
            float pa[4] = {pr.x, pr.y, pr.z, pr.w};
            float va[4] = {vr.x, vr.y, vr.z, vr.w};
#pragma unroll
            for (int i = 0; i < 4; i++)
#pragma unroll
                for (int j = 0; j < 4; j++) o[i][j] += pa[i] * va[j];
        }
        __syncthreads();  // before next tile overwrites KsT/Vs/PsT
    }

    // Normalize and store to (B,T,C)
#pragma unroll
    for (int i = 0; i < 4; i++) {
        float inv = 1.f / l_i[i];
        int row = qb * 64 + tr + i;
        float4 v = make_float4(o[i][0] * inv, o[i][1] * inv, o[i][2] * inv,
                               o[i][3] * inv);
        *(float4*)&g_O[((size_t)b * SEQ + row) * N_EMBD + h * 64 + tc] = v;
    }
}

// ---------------------------------------------------------------------------
extern "C" void kernel_launch(void* const* d_in, const int* in_sizes, int n_in,
                              void* d_out, int out_size)
{
    const float* x  = (const float*)d_in[0];
    const float* Wq = (const float*)d_in[1];
    const float* bq = (const float*)d_in[2];
    const float* Wk = (const float*)d_in[3];
    const float* bk = (const float*)d_in[4];
    const float* Wv = (const float*)d_in[5];
    const float* bv = (const float*)d_in[6];
    const float* Wp = (const float*)d_in[7];
    const float* bp = (const float*)d_in[8];
    float* out = (float*)d_out;

    cudaFuncSetAttribute(attn_kernel,
                         cudaFuncAttributeMaxDynamicSharedMemorySize,
                         ATTN_SMEM);

    dim3 gQKV(N_EMBD / BN, M_TOT / BM, 3);       // (8, 64, 3)
    qkv_gemm_kernel<<<gQKV, 256>>>(x, Wq, bq, Wk, bk, Wv, bv);

    dim3 gAtt(SEQ / 64, N_HEAD, BATCH);          // (32, 16, 4)
    attn_kernel<<<gAtt, 256, ATTN_SMEM>>>();

    dim3 gP(N_EMBD / BN, M_TOT / BM, 1);         // (8, 64)
    proj_gemm_kernel<<<gP, 256>>>(Wp, bp, out);
}

// round 2
// speedup vs baseline: 2.6915x; 2.6915x over previous
#include <cuda_runtime.h>
#include <math.h>

#define N_EMBD   1024
#define N_HEAD   16
#define HEAD_DIM 64
#define BATCH    4
#define SEQ      2048
#define M_TOT    (BATCH * SEQ)

// Scratch (__device__ globals; no runtime allocation allowed).
// Q/K/V stored as tf32-truncated fp32 bit patterns, layout (B,H,T,D).
__device__ float g_Q[(size_t)BATCH * N_HEAD * SEQ * HEAD_DIM];
__device__ float g_K[(size_t)BATCH * N_HEAD * SEQ * HEAD_DIM];
__device__ float g_V[(size_t)BATCH * N_HEAD * SEQ * HEAD_DIM];
__device__ float g_O[(size_t)BATCH * SEQ * N_EMBD];   // attention out, fp32 (B,T,C)

// ---------------------------------------------------------------------------
// tf32 helpers
// ---------------------------------------------------------------------------
__device__ __forceinline__ unsigned f2tf(float f) {
    unsigned u;
    asm("cvt.rna.tf32.f32 %0, %1;" : "=r"(u) : "f"(f));
    return u;
}

__device__ __forceinline__ void mma_tf32(float* d, const unsigned* a,
                                         const unsigned* b) {
    asm volatile(
        "mma.sync.aligned.m16n8k8.row.col.f32.tf32.tf32.f32 "
        "{%0,%1,%2,%3}, {%4,%5,%6,%7}, {%8,%9}, {%0,%1,%2,%3};"
        : "+f"(d[0]), "+f"(d[1]), "+f"(d[2]), "+f"(d[3])
        : "r"(a[0]), "r"(a[1]), "r"(a[2]), "r"(a[3]), "r"(b[0]), "r"(b[1]));
}

// ---------------------------------------------------------------------------
// GEMM: 128x128 block, BK=16, 256 threads (8 warps, 2x4), warp tile 64x32.
// ---------------------------------------------------------------------------
#define GBM 128
#define GBN 128
#define GBK 16
#define AS_STRIDE 20    // conflict-free for A-fragment pattern
#define BS_STRIDE 136   // conflict-free for B-fragment pattern

struct GemmAcc { float a[4][4][4]; };

// Computes acc for block tile (m0, n0) of X(tf32-converted on the fly) @ W.
// X is row-major [M][1024] fp32, W row-major [1024][1024] fp32.
__device__ __forceinline__ void gemm_tile_tf32(
    const float* __restrict__ X, const float* __restrict__ W,
    int m0, int n0, GemmAcc& acc)
{
    __shared__ unsigned As[GBM][AS_STRIDE];
    __shared__ unsigned Bs[GBK][BS_STRIDE];

    const int tid  = threadIdx.x;
    const int warp = tid >> 5, lane = tid & 31;
    const int wm = (warp >> 2) * 64, wn = (warp & 3) * 32;
    const int gr = lane >> 2, gc = lane & 3;

    const int arow = tid >> 1;
    const int acg  = (tid & 1) * 8;
    const int brow = tid >> 4;
    const int bcg  = (tid & 15) * 8;

#pragma unroll
    for (int mt = 0; mt < 4; mt++)
#pragma unroll
        for (int nt = 0; nt < 4; nt++)
#pragma unroll
            for (int j = 0; j < 4; j++) acc.a[mt][nt][j] = 0.f;

    for (int k0 = 0; k0 < N_EMBD; k0 += GBK) {
        // load + convert A tile
        const float* Ap = X + (size_t)(m0 + arow) * N_EMBD + k0 + acg;
        float4 a0 = *(const float4*)Ap;
        float4 a1 = *(const float4*)(Ap + 4);
        uint4 u0 = make_uint4(f2tf(a0.x), f2tf(a0.y), f2tf(a0.z), f2tf(a0.w));
        uint4 u1 = make_uint4(f2tf(a1.x), f2tf(a1.y), f2tf(a1.z), f2tf(a1.w));
        *(uint4*)&As[arow][acg]     = u0;
        *(uint4*)&As[arow][acg + 4] = u1;
        // load + convert B tile
        const float* Bp = W + (size_t)(k0 + brow) * N_EMBD + n0 + bcg;
        float4 b0 = *(const float4*)Bp;
        float4 b1 = *(const float4*)(Bp + 4);
        uint4 v0 = make_uint4(f2tf(b0.x), f2tf(b0.y), f2tf(b0.z), f2tf(b0.w));
        uint4 v1 = make_uint4(f2tf(b1.x), f2tf(b1.y), f2tf(b1.z), f2tf(b1.w));
        *(uint4*)&Bs[brow][bcg]     = v0;
        *(uint4*)&Bs[brow][bcg + 4] = v1;
        __syncthreads();

#pragma unroll
        for (int kk = 0; kk < GBK; kk += 8) {
            unsigned af[4][4];
#pragma unroll
            for (int mt = 0; mt < 4; mt++) {
                int m = wm + mt * 16;
                af[mt][0] = As[m + gr][kk + gc];
                af[mt][1] = As[m + gr + 8][kk + gc];
                af[mt][2] = As[m + gr][kk + gc + 4];
                af[mt][3] = As[m + gr + 8][kk + gc + 4];
            }
            unsigned bf[4][2];
#pragma unroll
            for (int nt = 0; nt < 4; nt++) {
                int n = wn + nt * 8;
                bf[nt][0] = Bs[kk + gc][n + gr];
                bf[nt][1] = Bs[kk + gc + 4][n + gr];
            }
#pragma unroll
            for (int mt = 0; mt < 4; mt++)
#pragma unroll
                for (int nt = 0; nt < 4; nt++)
                    mma_tf32(acc.a[mt][nt], af[mt], bf[nt]);
        }
        __syncthreads();
    }
}

// QKV projection -> permuted (B,H,T,D), stored tf32-truncated.
__global__ __launch_bounds__(256) void qkv_gemm_kernel(
    const float* __restrict__ X,
    const float* __restrict__ Wq, const float* __restrict__ bq,
    const float* __restrict__ Wk, const float* __restrict__ bk,
    const float* __restrict__ Wv, const float* __restrict__ bv)
{
    const int z = blockIdx.z;
    const float* W    = (z == 0) ? Wq : ((z == 1) ? Wk : Wv);
    const float* bias = (z == 0) ? bq : ((z == 1) ? bk : bv);
    float* out        = (z == 0) ? g_Q : ((z == 1) ? g_K : g_V);

    const int m0 = blockIdx.y * GBM;
    const int n0 = blockIdx.x * GBN;

    GemmAcc acc;
    gemm_tile_tf32(X, W, m0, n0, acc);

    const int tid  = threadIdx.x;
    const int warp = tid >> 5, lane = tid & 31;
    const int wm = (warp >> 2) * 64, wn = (warp & 3) * 32;
    const int gr = lane >> 2, gc = lane & 3;

#pragma unroll
    for (int mt = 0; mt < 4; mt++) {
#pragma unroll
        for (int nt = 0; nt < 4; nt++) {
            int n = n0 + wn + nt * 8 + 2 * gc;
            int h = n >> 6, d = n & 63;
            float bi0 = bias[n], bi1 = bias[n + 1];
#pragma unroll
            for (int half = 0; half < 2; half++) {
                int m = m0 + wm + mt * 16 + gr + half * 8;
                int b = m >> 11, t = m & (SEQ - 1);
                float c0 = acc.a[mt][nt][half * 2 + 0] + bi0;
                float c1 = acc.a[mt][nt][half * 2 + 1] + bi1;
                float2 v = make_float2(__uint_as_float(f2tf(c0)),
                                       __uint_as_float(f2tf(c1)));
                *(float2*)&out[(((size_t)(b * N_HEAD + h)) * SEQ + t) * 64 + d] = v;
            }
        }
    }
}

// Output projection: d_out = g_O @ Wp + bp (fp32 out).
__global__ __launch_bounds__(256) void proj_gemm_kernel(
    const float* __restrict__ Wp, const float* __restrict__ bp,
    float* __restrict__ out)
{
    const int m0 = blockIdx.y * GBM;
    const int n0 = blockIdx.x * GBN;

    GemmAcc acc;
    gemm_tile_tf32(g_O, Wp, m0, n0, acc);

    const int tid  = threadIdx.x;
    const int warp = tid >> 5, lane = tid & 31;
    const int wm = (warp >> 2) * 64, wn = (warp & 3) * 32;
    const int gr = lane >> 2, gc = lane & 3;

#pragma unroll
    for (int mt = 0; mt < 4; mt++) {
#pragma unroll
        for (int nt = 0; nt < 4; nt++) {
            int n = n0 + wn + nt * 8 + 2 * gc;
            float bi0 = bp[n], bi1 = bp[n + 1];
#pragma unroll
            for (int half = 0; half < 2; half++) {
                int m = m0 + wm + mt * 16 + gr + half * 8;
                float2 v = make_float2(acc.a[mt][nt][half * 2 + 0] + bi0,
                                       acc.a[mt][nt][half * 2 + 1] + bi1);
                *(float2*)&out[(size_t)m * N_EMBD + n] = v;
            }
        }
    }
}

// ---------------------------------------------------------------------------
// Fused causal attention, tf32 tensor cores.
// Block: (b, h, 128-query tile). 256 threads = 8 warps; warp owns a 16-row
// strip. Key tiles of 64. Softmax reductions live inside 4-lane shfl groups
// (mma C-fragment row ownership). P round-trips through smem as A-operand.
// ---------------------------------------------------------------------------
#define AQS 68
#define AKS 68
#define AVS 72
#define APS 68
// words: Qs 128*68 + Ks 64*68 + Vs 64*72 + Ps 128*68 = 26368 -> 105472 B
#define ATTN_SMEM_WORDS (128 * AQS + 64 * AKS + 64 * AVS + 128 * APS)
#define ATTN_SMEM_BYTES (ATTN_SMEM_WORDS * 4)

__global__ __launch_bounds__(256) void attn_kernel()
{
    extern __shared__ unsigned sm[];
    unsigned* Qs = sm;
    unsigned* Ks = Qs + 128 * AQS;
    unsigned* Vs = Ks + 64 * AKS;
    unsigned* Ps = Vs + 64 * AVS;

    const int qt = blockIdx.x;          // 0..15 (128-query tiles)
    const int h  = blockIdx.y;
    const int b  = blockIdx.z;
    const int tid  = threadIdx.x;
    const int warp = tid >> 5, lane = tid & 31;
    const int gr = lane >> 2, gc = lane & 3;
    const int rw = warp * 16;           // warp's row strip within the 128

    const int q0 = qt * 128;
    const float* Qg = g_Q + (((size_t)(b * N_HEAD + h)) * SEQ + q0) * 64;
    const float* Kb = g_K + ((size_t)(b * N_HEAD + h)) * SEQ * 64;
    const float* Vb = g_V + ((size_t)(b * N_HEAD + h)) * SEQ * 64;

    // Q tile copy (already tf32 patterns)
    for (int idx = tid; idx < 2048; idx += 256) {
        int r = idx >> 4, c4 = (idx & 15) * 4;
        *(uint4*)&Qs[r * AQS + c4] = *(const uint4*)&Qg[r * 64 + c4];
    }

    float m_[2] = {-1e30f, -1e30f};
    float l_[2] = {0.f, 0.f};
    float o[8][4];
#pragma unroll
    for (int dt = 0; dt < 8; dt++)
#pragma unroll
        for (int j = 0; j < 4; j++) o[dt][j] = 0.f;

    const int row0 = q0 + rw + gr;
    const int row1 = row0 + 8;
    const int wrow_max = q0 + rw + 15;
    const int nkt = qt * 2 + 2;         // key tiles to process

    for (int kb = 0; kb < nkt; kb++) {
        __syncthreads();
        const float* Kg = Kb + (size_t)kb * 64 * 64;
        const float* Vg = Vb + (size_t)kb * 64 * 64;
        for (int idx = tid; idx < 1024; idx += 256) {
            int r = idx >> 4, c4 = (idx & 15) * 4;
            *(uint4*)&Ks[r * AKS + c4] = *(const uint4*)&Kg[r * 64 + c4];
            *(uint4*)&Vs[r * AVS + c4] = *(const uint4*)&Vg[r * 64 + c4];
        }
        __syncthreads();

        if (kb * 64 > wrow_max) continue;   // warp's strip fully masked

        // S = Q K^T
        float s[8][4];
#pragma unroll
        for (int nt = 0; nt < 8; nt++)
#pragma unroll
            for (int j = 0; j < 4; j++) s[nt][j] = 0.f;

#pragma unroll
        for (int ch = 0; ch < 8; ch++) {
            int k = ch * 8;
            unsigned af[4];
            af[0] = Qs[(rw + gr) * AQS + k + gc];
            af[1] = Qs[(rw + gr + 8) * AQS + k + gc];
            af[2] = Qs[(rw + gr) * AQS + k + gc + 4];
            af[3] = Qs[(rw + gr + 8) * AQS + k + gc + 4];
#pragma unroll
            for (int nt = 0; nt < 8; nt++) {
                unsigned bf[2];
                bf[0] = Ks[(nt * 8 + gr) * AKS + k + gc];
                bf[1] = Ks[(nt * 8 + gr) * AKS + k + gc + 4];
                mma_tf32(s[nt], af, bf);
            }
        }

        // scale + causal mask
#pragma unroll
        for (int nt = 0; nt < 8; nt++) {
            int c0 = kb * 64 + nt * 8 + 2 * gc;
            s[nt][0] = (c0     > row0) ? -1e30f : s[nt][0] * 0.125f;
            s[nt][1] = (c0 + 1 > row0) ? -1e30f : s[nt][1] * 0.125f;
            s[nt][2] = (c0     > row1) ? -1e30f : s[nt][2] * 0.125f;
            s[nt][3] = (c0 + 1 > row1) ? -1e30f : s[nt][3] * 0.125f;
        }

        // online softmax (rows row0 and row1; 4-lane groups own a row)
        float mx0 = -1e30f, mx1 = -1e30f;
#pragma unroll
        for (int nt = 0; nt < 8; nt++) {
            mx0 = fmaxf(mx0, fmaxf(s[nt][0], s[nt][1]));
            mx1 = fmaxf(mx1, fmaxf(s[nt][2], s[nt][3]));
        }
#pragma unroll
        for (int off = 1; off < 4; off <<= 1) {
            mx0 = fmaxf(mx0, __shfl_xor_sync(0xffffffffu, mx0, off));
            mx1 = fmaxf(mx1, __shfl_xor_sync(0xffffffffu, mx1, off));
        }
        float mn0 = fmaxf(m_[0], mx0), mn1 = fmaxf(m_[1], mx1);
        float sc0 = __expf(m_[0] - mn0), sc1 = __expf(m_[1] - mn1);
        float sum0 = 0.f, sum1 = 0.f;
#pragma unroll
        for (int nt = 0; nt < 8; nt++) {
            s[nt][0] = __expf(s[nt][0] - mn0);
            s[nt][1] = __expf(s[nt][1] - mn0);
            s[nt][2] = __expf(s[nt][2] - mn1);
            s[nt][3] = __expf(s[nt][3] - mn1);
            sum0 += s[nt][0] + s[nt][1];
            sum1 += s[nt][2] + s[nt][3];
        }
#pragma unroll
        for (int off = 1; off < 4; off <<= 1) {
            sum0 += __shfl_xor_sync(0xffffffffu, sum0, off);
            sum1 += __shfl_xor_sync(0xffffffffu, sum1, off);
        }
        l_[0] = l_[0] * sc0 + sum0;
        l_[1] = l_[1] * sc1 + sum1;
        m_[0] = mn0;
        m_[1] = mn1;
#pragma unroll
        for (int dt = 0; dt < 8; dt++) {
            o[dt][0] *= sc0; o[dt][1] *= sc0;
            o[dt][2] *= sc1; o[dt][3] *= sc1;
        }

        // publish P (tf32) into this warp's private strip of Ps
#pragma unroll
        for (int nt = 0; nt < 8; nt++) {
            int c = nt * 8 + 2 * gc;
            Ps[(rw + gr) * APS + c]         = f2tf(s[nt][0]);
            Ps[(rw + gr) * APS + c + 1]     = f2tf(s[nt][1]);
            Ps[(rw + gr + 8) * APS + c]     = f2tf(s[nt][2]);
            Ps[(rw + gr + 8) * APS + c + 1] = f2tf(s[nt][3]);
        }
        __syncwarp();

        // O += P @ V
#pragma unroll
        for (int ch = 0; ch < 8; ch++) {
            int ss = ch * 8;
            unsigned pa[4];
            pa[0] = Ps[(rw + gr) * APS + ss + gc];
            pa[1] = Ps[(rw + gr + 8) * APS + ss + gc];
            pa[2] = Ps[(rw + gr) * APS + ss + gc + 4];
            pa[3] = Ps[(rw + gr + 8) * APS + ss + gc + 4];
#pragma unroll
            for (int dt = 0; dt < 8; dt++) {
                unsigned bf[2];
                bf[0] = Vs[(ss + gc) * AVS + dt * 8 + gr];
                bf[1] = Vs[(ss + gc + 4) * AVS + dt * 8 + gr];
                mma_tf32(o[dt], pa, bf);
            }
        }
    }

    // normalize + store fp32 to g_O (B,T,C)
    float inv0 = 1.f / l_[0];
    float inv1 = 1.f / l_[1];
#pragma unroll
    for (int dt = 0; dt < 8; dt++) {
        int col = h * 64 + dt * 8 + 2 * gc;
        float2 v0 = make_float2(o[dt][0] * inv0, o[dt][1] * inv0);
        float2 v1 = make_float2(o[dt][2] * inv1, o[dt][3] * inv1);
        *(float2*)&g_O[((size_t)b * SEQ + row0) * N_EMBD + col] = v0;
        *(float2*)&g_O[((size_t)b * SEQ + row1) * N_EMBD + col] = v1;
    }
}

// ---------------------------------------------------------------------------
extern "C" void kernel_launch(void* const* d_in, const int* in_sizes, int n_in,
                              void* d_out, int out_size)
{
    const float* x  = (const float*)d_in[0];
    const float* Wq = (const float*)d_in[1];
    const float* bq = (const float*)d_in[2];
    const float* Wk = (const float*)d_in[3];
    const float* bk = (const float*)d_in[4];
    const float* Wv = (const float*)d_in[5];
    const float* bv = (const float*)d_in[6];
    const float* Wp = (const float*)d_in[7];
    const float* bp = (const float*)d_in[8];
    float* out = (float*)d_out;

    cudaFuncSetAttribute(attn_kernel,
                         cudaFuncAttributeMaxDynamicSharedMemorySize,
                         ATTN_SMEM_BYTES);

    dim3 gQKV(N_EMBD / GBN, M_TOT / GBM, 3);     // (8, 64, 3)
    qkv_gemm_kernel<<<gQKV, 256>>>(x, Wq, bq, Wk, bk, Wv, bv);

    dim3 gAtt(SEQ / 128, N_HEAD, BATCH);         // (16, 16, 4)
    attn_kernel<<<gAtt, 256, ATTN_SMEM_BYTES>>>();

    dim3 gP(N_EMBD / GBN, M_TOT / GBM, 1);       // (8, 64)
    proj_gemm_kernel<<<gP, 256>>>(Wp, bp, out);
}

// round 3
// speedup vs baseline: 2.8584x; 1.0620x over previous
#include <cuda_runtime.h>
#include <math.h>

#define N_EMBD   1024
#define N_HEAD   16
#define HEAD_DIM 64
#define BATCH    4
#define SEQ      2048
#define M_TOT    (BATCH * SEQ)

// Scratch (__device__ globals). Q/K/V hold tf32-truncated patterns, (B,H,T,D).
__device__ float g_Q[(size_t)BATCH * N_HEAD * SEQ * HEAD_DIM];
__device__ float g_K[(size_t)BATCH * N_HEAD * SEQ * HEAD_DIM];
__device__ float g_V[(size_t)BATCH * N_HEAD * SEQ * HEAD_DIM];
__device__ float g_O[(size_t)BATCH * SEQ * N_EMBD];

// ---------------------------------------------------------------------------
__device__ __forceinline__ unsigned f2tf(float f) {
    unsigned u;
    asm("cvt.rna.tf32.f32 %0, %1;" : "=r"(u) : "f"(f));
    return u;
}

__device__ __forceinline__ void mma_tf32(float* d, const unsigned* a,
                                         const unsigned* b) {
    asm volatile(
        "mma.sync.aligned.m16n8k8.row.col.f32.tf32.tf32.f32 "
        "{%0,%1,%2,%3}, {%4,%5,%6,%7}, {%8,%9}, {%0,%1,%2,%3};"
        : "+f"(d[0]), "+f"(d[1]), "+f"(d[2]), "+f"(d[3])
        : "r"(a[0]), "r"(a[1]), "r"(a[2]), "r"(a[3]), "r"(b[0]), "r"(b[1]));
}

__device__ __forceinline__ void cp16(void* smem_dst, const void* gsrc) {
    unsigned u = (unsigned)__cvta_generic_to_shared(smem_dst);
    asm volatile("cp.async.cg.shared.global [%0], [%1], 16;\n"
                 :: "r"(u), "l"(gsrc));
}
#define CP_COMMIT() asm volatile("cp.async.commit_group;\n" ::: "memory")
#define CP_WAIT(N)  asm volatile("cp.async.wait_group %0;\n" :: "n"(N) : "memory")

// ---------------------------------------------------------------------------
// GEMM: 128x128 block, BK=16, 256 threads (8 warps, 2x4), warp tile 64x32.
// Double-buffered smem, register prefetch: one barrier per K-step.
// ---------------------------------------------------------------------------
#define GBM 128
#define GBN 128
#define GBK 16
#define AS_STRIDE 20
#define BS_STRIDE 136

struct GemmAcc { float a[4][4][4]; };

__device__ __forceinline__ void gemm_tile_tf32(
    const float* __restrict__ X, const float* __restrict__ W,
    int m0, int n0, GemmAcc& acc)
{
    __shared__ unsigned As[2][GBM][AS_STRIDE];
    __shared__ unsigned Bs[2][GBK][BS_STRIDE];

    const int tid  = threadIdx.x;
    const int warp = tid >> 5, lane = tid & 31;
    const int wm = (warp >> 2) * 64, wn = (warp & 3) * 32;
    const int gr = lane >> 2, gc = lane & 3;

    const int arow = tid >> 1;
    const int acg  = (tid & 1) * 8;
    const int brow = tid >> 4;
    const int bcg  = (tid & 15) * 8;

#pragma unroll
    for (int mt = 0; mt < 4; mt++)
#pragma unroll
        for (int nt = 0; nt < 4; nt++)
#pragma unroll
            for (int j = 0; j < 4; j++) acc.a[mt][nt][j] = 0.f;

    const float* Arow = X + (size_t)(m0 + arow) * N_EMBD + acg;
    const float* Brow = W + (size_t)brow * N_EMBD + n0 + bcg;

    float4 a0, a1, b0, b1;
    // prologue: tile k0=0
    a0 = *(const float4*)(Arow);
    a1 = *(const float4*)(Arow + 4);
    b0 = *(const float4*)(Brow);
    b1 = *(const float4*)(Brow + 4);
    {
        *(uint4*)&As[0][arow][acg] =
            make_uint4(f2tf(a0.x), f2tf(a0.y), f2tf(a0.z), f2tf(a0.w));
        *(uint4*)&As[0][arow][acg + 4] =
            make_uint4(f2tf(a1.x), f2tf(a1.y), f2tf(a1.z), f2tf(a1.w));
        *(uint4*)&Bs[0][brow][bcg] =
            make_uint4(f2tf(b0.x), f2tf(b0.y), f2tf(b0.z), f2tf(b0.w));
        *(uint4*)&Bs[0][brow][bcg + 4] =
            make_uint4(f2tf(b1.x), f2tf(b1.y), f2tf(b1.z), f2tf(b1.w));
    }
    __syncthreads();

    int cur = 0;
    for (int k0 = 0; k0 < N_EMBD; k0 += GBK) {
        const bool has_next = (k0 + GBK) < N_EMBD;
        if (has_next) {
            a0 = *(const float4*)(Arow + k0 + GBK);
            a1 = *(const float4*)(Arow + k0 + GBK + 4);
            b0 = *(const float4*)(Brow + (size_t)(k0 + GBK) * N_EMBD);
            b1 = *(const float4*)(Brow + (size_t)(k0 + GBK) * N_EMBD + 4);
        }

#pragma unroll
        for (int kk = 0; kk < GBK; kk += 8) {
            unsigned af[4][4];
#pragma unroll
            for (int mt = 0; mt < 4; mt++) {
                int m = wm + mt * 16;
                af[mt][0] = As[cur][m + gr][kk + gc];
                af[mt][1] = As[cur][m + gr + 8][kk + gc];
                af[mt][2] = As[cur][m + gr][kk + gc + 4];
                af[mt][3] = As[cur][m + gr + 8][kk + gc + 4];
            }
            unsigned bf[4][2];
#pragma unroll
            for (int nt = 0; nt < 4; nt++) {
                int n = wn + nt * 8;
                bf[nt][0] = Bs[cur][kk + gc][n + gr];
                bf[nt][1] = Bs[cur][kk + gc + 4][n + gr];
            }
#pragma unroll
            for (int mt = 0; mt < 4; mt++)
#pragma unroll
                for (int nt = 0; nt < 4; nt++)
                    mma_tf32(acc.a[mt][nt], af[mt], bf[nt]);
        }

        if (has_next) {
            int nxt = cur ^ 1;
            *(uint4*)&As[nxt][arow][acg] =
                make_uint4(f2tf(a0.x), f2tf(a0.y), f2tf(a0.z), f2tf(a0.w));
            *(uint4*)&As[nxt][arow][acg + 4] =
                make_uint4(f2tf(a1.x), f2tf(a1.y), f2tf(a1.z), f2tf(a1.w));
            *(uint4*)&Bs[nxt][brow][bcg] =
                make_uint4(f2tf(b0.x), f2tf(b0.y), f2tf(b0.z), f2tf(b0.w));
            *(uint4*)&Bs[nxt][brow][bcg + 4] =
                make_uint4(f2tf(b1.x), f2tf(b1.y), f2tf(b1.z), f2tf(b1.w));
            __syncthreads();
            cur = nxt;
        }
    }
}

__global__ __launch_bounds__(256, 2) void qkv_gemm_kernel(
    const float* __restrict__ X,
    const float* __restrict__ Wq, const float* __restrict__ bq,
    const float* __restrict__ Wk, const float* __restrict__ bk,
    const float* __restrict__ Wv, const float* __restrict__ bv)
{
    const int z = blockIdx.z;
    const float* W    = (z == 0) ? Wq : ((z == 1) ? Wk : Wv);
    const float* bias = (z == 0) ? bq : ((z == 1) ? bk : bv);
    float* out        = (z == 0) ? g_Q : ((z == 1) ? g_K : g_V);

    const int m0 = blockIdx.y * GBM;
    const int n0 = blockIdx.x * GBN;

    GemmAcc acc;
    gemm_tile_tf32(X, W, m0, n0, acc);

    const int tid  = threadIdx.x;
    const int warp = tid >> 5, lane = tid & 31;
    const int wm = (warp >> 2) * 64, wn = (warp & 3) * 32;
    const int gr = lane >> 2, gc = lane & 3;

#pragma unroll
    for (int mt = 0; mt < 4; mt++) {
#pragma unroll
        for (int nt = 0; nt < 4; nt++) {
            int n = n0 + wn + nt * 8 + 2 * gc;
            int h = n >> 6, d = n & 63;
            float bi0 = bias[n], bi1 = bias[n + 1];
#pragma unroll
            for (int half = 0; half < 2; half++) {
                int m = m0 + wm + mt * 16 + gr + half * 8;
                int b = m >> 11, t = m & (SEQ - 1);
                float c0 = acc.a[mt][nt][half * 2 + 0] + bi0;
                float c1 = acc.a[mt][nt][half * 2 + 1] + bi1;
                float2 v = make_float2(__uint_as_float(f2tf(c0)),
                                       __uint_as_float(f2tf(c1)));
                *(float2*)&out[(((size_t)(b * N_HEAD + h)) * SEQ + t) * 64 + d] = v;
            }
        }
    }
}

__global__ __launch_bounds__(256, 2) void proj_gemm_kernel(
    const float* __restrict__ Wp, const float* __restrict__ bp,
    float* __restrict__ out)
{
    const int m0 = blockIdx.y * GBM;
    const int n0 = blockIdx.x * GBN;

    GemmAcc acc;
    gemm_tile_tf32(g_O, Wp, m0, n0, acc);

    const int tid  = threadIdx.x;
    const int warp = tid >> 5, lane = tid & 31;
    const int wm = (warp >> 2) * 64, wn = (warp & 3) * 32;
    const int gr = lane >> 2, gc = lane & 3;

#pragma unroll
    for (int mt = 0; mt < 4; mt++) {
#pragma unroll
        for (int nt = 0; nt < 4; nt++) {
            int n = n0 + wn + nt * 8 + 2 * gc;
            float bi0 = bp[n], bi1 = bp[n + 1];
#pragma unroll
            for (int half = 0; half < 2; half++) {
                int m = m0 + wm + mt * 16 + gr + half * 8;
                float2 v = make_float2(acc.a[mt][nt][half * 2 + 0] + bi0,
                                       acc.a[mt][nt][half * 2 + 1] + bi1);
                *(float2*)&out[(size_t)m * N_EMBD + n] = v;
            }
        }
    }
}

// ---------------------------------------------------------------------------
// Fused causal attention, tf32 tensor cores, cp.async double-buffered K/V.
// Block: (b,h,128-query tile), 256 threads = 8 warps, warp owns 16-row strip.
// Key tiles of 32. Softmax in 4-lane shfl groups.
// ---------------------------------------------------------------------------
#define AQS 68
#define AKS 68
#define AVS 72
#define APS 36
#define QS_WORDS   (128 * AQS)        // 8704
#define KS_WORDS   (32 * AKS)         // 2176 per buffer
#define VS_WORDS   (32 * AVS)         // 2304 per buffer
#define PS_WORDS   (128 * APS)        // 4608
#define ATTN_SMEM_BYTES ((QS_WORDS + 2 * KS_WORDS + 2 * VS_WORDS + PS_WORDS) * 4)

__global__ __launch_bounds__(256) void attn_kernel()
{
    extern __shared__ unsigned sm[];
    unsigned* Qs  = sm;
    unsigned* Ks0 = Qs + QS_WORDS;
    unsigned* Vs0 = Ks0 + 2 * KS_WORDS;
    unsigned* Ps  = Vs0 + 2 * VS_WORDS;

    const int qt = blockIdx.x;
    const int h  = blockIdx.y;
    const int b  = blockIdx.z;
    const int tid  = threadIdx.x;
    const int warp = tid >> 5, lane = tid & 31;
    const int gr = lane >> 2, gc = lane & 3;
    const int rw = warp * 16;

    const int q0 = qt * 128;
    const float* Qg = g_Q + (((size_t)(b * N_HEAD + h)) * SEQ + q0) * 64;
    const float* Kb = g_K + ((size_t)(b * N_HEAD + h)) * SEQ * 64;
    const float* Vb = g_V + ((size_t)(b * N_HEAD + h)) * SEQ * 64;

    const int nkt = 4 * qt + 4;       // 32-key tiles needed

    // issue tile 0 (K+V) via cp.async
    {
        const float* Kg = Kb;
        const float* Vg = Vb;
#pragma unroll
        for (int i = 0; i < 2; i++) {
            int idx = tid + i * 256;
            int r = idx >> 4, c4 = (idx & 15) * 4;
            cp16(&Ks0[r * AKS + c4], Kg + r * 64 + c4);
            cp16(&Vs0[r * AVS + c4], Vg + r * 64 + c4);
        }
        CP_COMMIT();
    }

    // Q tile copy (tf32 patterns already)
    for (int idx = tid; idx < 2048; idx += 256) {
        int r = idx >> 4, c4 = (idx & 15) * 4;
        *(uint4*)&Qs[r * AQS + c4] = *(const uint4*)&Qg[r * 64 + c4];
    }

    float m_[2] = {-1e30f, -1e30f};
    float l_[2] = {0.f, 0.f};
    float o[8][4];
#pragma unroll
    for (int dt = 0; dt < 8; dt++)
#pragma unroll
        for (int j = 0; j < 4; j++) o[dt][j] = 0.f;

    const int row0 = q0 + rw + gr;
    const int row1 = row0 + 8;
    const int wrow_max = q0 + rw + 15;

    for (int kb = 0; kb < nkt; kb++) {
        const bool has_next = (kb + 1) < nkt;
        __syncthreads();   // all warps done with compute(kb-1): buf (kb+1)&1 free
        if (has_next) {
            const float* Kg = Kb + (size_t)(kb + 1) * 32 * 64;
            const float* Vg = Vb + (size_t)(kb + 1) * 32 * 64;
            unsigned* Kd = Ks0 + ((kb + 1) & 1) * KS_WORDS;
            unsigned* Vd = Vs0 + ((kb + 1) & 1) * VS_WORDS;
#pragma unroll
            for (int i = 0; i < 2; i++) {
                int idx = tid + i * 256;
                int r = idx >> 4, c4 = (idx & 15) * 4;
                cp16(&Kd[r * AKS + c4], Kg + r * 64 + c4);
                cp16(&Vd[r * AVS + c4], Vg + r * 64 + c4);
            }
            CP_COMMIT();
            CP_WAIT(1);
        } else {
            CP_WAIT(0);
        }
        __syncthreads();   // tile kb visible to all

        if (kb * 32 > wrow_max) continue;   // fully masked for this warp

        const unsigned* Kt = Ks0 + (kb & 1) * KS_WORDS;
        const unsigned* Vt = Vs0 + (kb & 1) * VS_WORDS;

        // S = Q K^T  (16 x 32)
        float s[4][4];
#pragma unroll
        for (int nt = 0; nt < 4; nt++)
#pragma unroll
            for (int j = 0; j < 4; j++) s[nt][j] = 0.f;

#pragma unroll
        for (int ch = 0; ch < 8; ch++) {
            int k = ch * 8;
            unsigned af[4];
            af[0] = Qs[(rw + gr) * AQS + k + gc];
            af[1] = Qs[(rw + gr + 8) * AQS + k + gc];
            af[2] = Qs[(rw + gr) * AQS + k + gc + 4];
            af[3] = Qs[(rw + gr + 8) * AQS + k + gc + 4];
#pragma unroll
            for (int nt = 0; nt < 4; nt++) {
                unsigned bf[2];
                bf[0] = Kt[(nt * 8 + gr) * AKS + k + gc];
                bf[1] = Kt[(nt * 8 + gr) * AKS + k + gc + 4];
                mma_tf32(s[nt], af, bf);
            }
        }

        // scale + causal mask
#pragma unroll
        for (int nt = 0; nt < 4; nt++) {
            int c0 = kb * 32 + nt * 8 + 2 * gc;
            s[nt][0] = (c0     > row0) ? -1e30f : s[nt][0] * 0.125f;
            s[nt][1] = (c0 + 1 > row0) ? -1e30f : s[nt][1] * 0.125f;
            s[nt][2] = (c0     > row1) ? -1e30f : s[nt][2] * 0.125f;
            s[nt][3] = (c0 + 1 > row1) ? -1e30f : s[nt][3] * 0.125f;
        }

        // online softmax
        float mx0 = -1e30f, mx1 = -1e30f;
#pragma unroll
        for (int nt = 0; nt < 4; nt++) {
            mx0 = fmaxf(mx0, fmaxf(s[nt][0], s[nt][1]));
            mx1 = fmaxf(mx1, fmaxf(s[nt][2], s[nt][3]));
        }
#pragma unroll
        for (int off = 1; off < 4; off <<= 1) {
            mx0 = fmaxf(mx0, __shfl_xor_sync(0xffffffffu, mx0, off));
            mx1 = fmaxf(mx1, __shfl_xor_sync(0xffffffffu, mx1, off));
        }
        float mn0 = fmaxf(m_[0], mx0), mn1 = fmaxf(m_[1], mx1);
        float sc0 = __expf(m_[0] - mn0), sc1 = __expf(m_[1] - mn1);
        float sum0 = 0.f, sum1 = 0.f;
#pragma unroll
        for (int nt = 0; nt < 4; nt++) {
            s[nt][0] = __expf(s[nt][0] - mn0);
            s[nt][1] = __expf(s[nt][1] - mn0);
            s[nt][2] = __expf(s[nt][2] - mn1);
            s[nt][3] = __expf(s[nt][3] - mn1);
            sum0 += s[nt][0] + s[nt][1];
            sum1 += s[nt][2] + s[nt][3];
        }
#pragma unroll
        for (int off = 1; off < 4; off <<= 1) {
            sum0 += __shfl_xor_sync(0xffffffffu, sum0, off);
            sum1 += __shfl_xor_sync(0xffffffffu, sum1, off);
        }
        l_[0] = l_[0] * sc0 + sum0;
        l_[1] = l_[1] * sc1 + sum1;
        m_[0] = mn0;
        m_[1] = mn1;
#pragma unroll
        for (int dt = 0; dt < 8; dt++) {
            o[dt][0] *= sc0; o[dt][1] *= sc0;
            o[dt][2] *= sc1; o[dt][3] *= sc1;
        }

        // publish P (tf32) into warp-private Ps strip
#pragma unroll
        for (int nt = 0; nt < 4; nt++) {
            int c = nt * 8 + 2 * gc;
            Ps[(rw + gr) * APS + c]         = f2tf(s[nt][0]);
            Ps[(rw + gr) * APS + c + 1]     = f2tf(s[nt][1]);
            Ps[(rw + gr + 8) * APS + c]     = f2tf(s[nt][2]);
            Ps[(rw + gr + 8) * APS + c + 1] = f2tf(s[nt][3]);
        }
        __syncwarp();

        // O += P @ V
#pragma unroll
        for (int ch = 0; ch < 4; ch++) {
            int ss = ch * 8;
            unsigned pa[4];
            pa[0] = Ps[(rw + gr) * APS + ss + gc];
            pa[1] = Ps[(rw + gr + 8) * APS + ss + gc];
            pa[2] = Ps[(rw + gr) * APS + ss + gc + 4];
            pa[3] = Ps[(rw + gr + 8) * APS + ss + gc + 4];
#pragma unroll
            for (int dt = 0; dt < 8; dt++) {
                unsigned bf[2];
                bf[0] = Vt[(ss + gc) * AVS + dt * 8 + gr];
                bf[1] = Vt[(ss + gc + 4) * AVS + dt * 8 + gr];
                mma_tf32(o[dt], pa, bf);
            }
        }
    }

    // normalize + store fp32 to g_O (B,T,C)
    float inv0 = 1.f / l_[0];
    float inv1 = 1.f / l_[1];
#pragma unroll
    for (int dt = 0; dt < 8; dt++) {
        int col = h * 64 + dt * 8 + 2 * gc;
        float2 v0 = make_float2(o[dt][0] * inv0, o[dt][1] * inv0);
        float2 v1 = make_float2(o[dt][2] * inv1, o[dt][3] * inv1);
        *(float2*)&g_O[((size_t)b * SEQ + row0) * N_EMBD + col] = v0;
        *(float2*)&g_O[((size_t)b * SEQ + row1) * N_EMBD + col] = v1;
    }
}

// ---------------------------------------------------------------------------
extern "C" void kernel_launch(void* const* d_in, const int* in_sizes, int n_in,
                              void* d_out, int out_size)
{
    const float* x  = (const float*)d_in[0];
    const float* Wq = (const float*)d_in[1];
    const float* bq = (const float*)d_in[2];
    const float* Wk = (const float*)d_in[3];
    const float* bk = (const float*)d_in[4];
    const float* Wv = (const float*)d_in[5];
    const float* bv = (const float*)d_in[6];
    const float* Wp = (const float*)d_in[7];
    const float* bp = (const float*)d_in[8];
    float* out = (float*)d_out;

    cudaFuncSetAttribute(attn_kernel,
                         cudaFuncAttributeMaxDynamicSharedMemorySize,
                         ATTN_SMEM_BYTES);

    dim3 gQKV(N_EMBD / GBN, M_TOT / GBM, 3);     // (8, 64, 3)
    qkv_gemm_kernel<<<gQKV, 256>>>(x, Wq, bq, Wk, bk, Wv, bv);

    dim3 gAtt(SEQ / 128, N_HEAD, BATCH);         // (16, 16, 4)
    attn_kernel<<<gAtt, 256, ATTN_SMEM_BYTES>>>();

    dim3 gP(N_EMBD / GBN, M_TOT / GBM, 1);       // (8, 64)
    proj_gemm_kernel<<<gP, 256>>>(Wp, bp, out);
}

// round 5
// speedup vs baseline: 5.1310x; 1.7951x over previous
#include <cuda_runtime.h>
#include <cuda_fp16.h>
#include <math.h>
#include <stdint.h>

#define N_EMBD   1024
#define N_HEAD   16
#define HEAD_DIM 64
#define BATCH    4
#define SEQ      2048
#define M_TOT    8192

// ---------------------------------------------------------------------------
// Device scratch (fp16). V stored transposed (B,H,D,T); Q,K as (B,H,T,D).
// ---------------------------------------------------------------------------
__device__ __half g_X[(size_t)M_TOT * N_EMBD];
__device__ __half g_Wt[4][(size_t)N_EMBD * N_EMBD];   // W^T [n][k]
__device__ __half g_Q[(size_t)BATCH * N_HEAD * SEQ * HEAD_DIM];
__device__ __half g_K[(size_t)BATCH * N_HEAD * SEQ * HEAD_DIM];
__device__ __half g_V[(size_t)BATCH * N_HEAD * HEAD_DIM * SEQ]; // (B,H,D,T)
__device__ __half g_O[(size_t)M_TOT * N_EMBD];        // attn out (B,T,C)

// ---------------------------------------------------------------------------
__device__ __forceinline__ void mma_fp16(float* d, const unsigned* a,
                                         const unsigned* b) {
    asm volatile(
        "mma.sync.aligned.m16n8k16.row.col.f32.f16.f16.f32 "
        "{%0,%1,%2,%3}, {%4,%5,%6,%7}, {%8,%9}, {%0,%1,%2,%3};"
        : "+f"(d[0]), "+f"(d[1]), "+f"(d[2]), "+f"(d[3])
        : "r"(a[0]), "r"(a[1]), "r"(a[2]), "r"(a[3]), "r"(b[0]), "r"(b[1]));
}

__device__ __forceinline__ void cp16(void* smem_dst, const void* gsrc) {
    unsigned u = (unsigned)__cvta_generic_to_shared(smem_dst);
    asm volatile("cp.async.cg.shared.global [%0], [%1], 16;\n"
                 :: "r"(u), "l"(gsrc));
}
__device__ __forceinline__ void cp8(void* smem_dst, const void* gsrc) {
    unsigned u = (unsigned)__cvta_generic_to_shared(smem_dst);
    asm volatile("cp.async.ca.shared.global [%0], [%1], 8;\n"
                 :: "r"(u), "l"(gsrc));
}
#define CP_COMMIT() asm volatile("cp.async.commit_group;\n" ::: "memory")
#define CP_WAIT(N)  asm volatile("cp.async.wait_group %0;\n" :: "n"(N) : "memory")

__device__ __forceinline__ unsigned h2u(__half2 h) {
    return *(unsigned*)&h;
}

// ---------------------------------------------------------------------------
// prep kernels
// ---------------------------------------------------------------------------
__global__ void prep_x_kernel(const float* __restrict__ x) {
    size_t i = (size_t)blockIdx.x * 256 + threadIdx.x;   // per 4 floats
    float4 v = ((const float4*)x)[i];
    uint2 u;
    u.x = h2u(__floats2half2_rn(v.x, v.y));
    u.y = h2u(__floats2half2_rn(v.z, v.w));
    ((uint2*)g_X)[i] = u;
}

__global__ void prep_w_kernel(const float* __restrict__ Wq,
                              const float* __restrict__ Wk,
                              const float* __restrict__ Wv,
                              const float* __restrict__ Wp) {
    __shared__ float tile[32][33];
    int z = blockIdx.z;
    const float* W = (z == 0) ? Wq : (z == 1) ? Wk : (z == 2) ? Wv : Wp;
    int x0 = blockIdx.x * 32;   // n
    int y0 = blockIdx.y * 32;   // k
    int tx = threadIdx.x;
    for (int i = threadIdx.y; i < 32; i += 8)
        tile[i][tx] = W[(size_t)(y0 + i) * N_EMBD + x0 + tx];
    __syncthreads();
    for (int i = threadIdx.y; i < 32; i += 8)
        g_Wt[z][(size_t)(x0 + i) * N_EMBD + y0 + tx] = __float2half(tile[tx][i]);
}

// ---------------------------------------------------------------------------
// fp16 GEMM: block 128(M) x 256(N), 8 warps (2x4) of 64x64, BK=32,
// cp.async double-buffered. Strides in halves: 40 (word-stride 20 -> CF).
// smem halves: As[2][128*40]=10240, Bs[2][256*40]=20480 -> 61440 bytes.
// ---------------------------------------------------------------------------
#define GSTR 40
#define AS_OFF(buf) ((buf) * 5120)
#define BS_OFF(buf) (10240 + (buf) * 10240)
#define GEMM_SMEM_BYTES 61440

__device__ __forceinline__ void gemm_load_stage(
    const __half* __restrict__ A, const __half* __restrict__ Bt,
    int m0, int n0, int kb, __half* smem, int buf, int tid)
{
    const int k0 = kb * 32;
#pragma unroll
    for (int i = 0; i < 4; i++) {
        int idx = tid + i * 256;
        int r = idx >> 3, ch = idx & 7;
        cp8(smem + AS_OFF(buf) + r * GSTR + ch * 4,
            A + (size_t)(m0 + r) * N_EMBD + k0 + ch * 4);
    }
#pragma unroll
    for (int i = 0; i < 8; i++) {
        int idx = tid + i * 256;
        int r = idx >> 3, ch = idx & 7;
        cp8(smem + BS_OFF(buf) + r * GSTR + ch * 4,
            Bt + (size_t)(n0 + r) * N_EMBD + k0 + ch * 4);
    }
}

__device__ __forceinline__ void gemm_fp16_main(
    const __half* __restrict__ A, const __half* __restrict__ Bt,
    int m0, int n0, __half* smem, float acc[4][8][4])
{
    const int tid = threadIdx.x;
    const int warp = tid >> 5, lane = tid & 31;
    const int wm = (warp >> 2) * 64;       // warpM in {0,1}
    const int wn = (warp & 3) * 64;        // warpN in {0..3}
    const int gr = lane >> 2, gc = lane & 3;

#pragma unroll
    for (int mt = 0; mt < 4; mt++)
#pragma unroll
        for (int nt = 0; nt < 8; nt++)
#pragma unroll
            for (int j = 0; j < 4; j++) acc[mt][nt][j] = 0.f;

    gemm_load_stage(A, Bt, m0, n0, 0, smem, 0, tid);
    CP_COMMIT();

    for (int kb = 0; kb < 32; kb++) {
        __syncthreads();                    // prior compute done; buf free
        if (kb + 1 < 32) {
            gemm_load_stage(A, Bt, m0, n0, kb + 1, smem, (kb + 1) & 1, tid);
            CP_COMMIT();
            CP_WAIT(1);
        } else {
            CP_WAIT(0);
        }
        __syncthreads();                    // stage kb visible

        const __half* Ab = smem + AS_OFF(kb & 1);
        const __half* Bb = smem + BS_OFF(kb & 1);
#pragma unroll
        for (int kk = 0; kk < 32; kk += 16) {
            unsigned af[4][4];
#pragma unroll
            for (int mt = 0; mt < 4; mt++) {
                const __half* p = Ab + (wm + mt * 16 + gr) * GSTR + kk + 2 * gc;
                af[mt][0] = *(const unsigned*)p;
                af[mt][1] = *(const unsigned*)(p + 8 * GSTR);
                af[mt][2] = *(const unsigned*)(p + 8);
                af[mt][3] = *(const unsigned*)(p + 8 * GSTR + 8);
            }
            unsigned bf[8][2];
#pragma unroll
            for (int nt = 0; nt < 8; nt++) {
                const __half* p = Bb + (wn + nt * 8 + gr) * GSTR + kk + 2 * gc;
                bf[nt][0] = *(const unsigned*)p;
                bf[nt][1] = *(const unsigned*)(p + 8);
            }
#pragma unroll
            for (int mt = 0; mt < 4; mt++)
#pragma unroll
                for (int nt = 0; nt < 8; nt++)
                    mma_fp16(acc[mt][nt], af[mt], bf[nt]);
        }
    }
}

// QKV: out Q/K (B,H,T,D) half; V (B,H,D,T) half. +bias.
__global__ __launch_bounds__(256, 1) void qkv_gemm_kernel(
    const float* __restrict__ bq, const float* __restrict__ bk,
    const float* __restrict__ bv)
{
    extern __shared__ __half smem[];
    const int z = blockIdx.z;
    const float* bias = (z == 0) ? bq : (z == 1) ? bk : bv;
    __half* out = (z == 0) ? g_Q : (z == 1) ? g_K : g_V;
    const int m0 = blockIdx.y * 128, n0 = blockIdx.x * 256;

    float acc[4][8][4];
    gemm_fp16_main(g_X, g_Wt[z], m0, n0, smem, acc);

    const int tid = threadIdx.x;
    const int warp = tid >> 5, lane = tid & 31;
    const int wm = (warp >> 2) * 64, wn = (warp & 3) * 64;
    const int gr = lane >> 2, gc = lane & 3;

#pragma unroll
    for (int mt = 0; mt < 4; mt++) {
#pragma unroll
        for (int nt = 0; nt < 8; nt++) {
            int n = n0 + wn + nt * 8 + 2 * gc;
            int h = n >> 6, d = n & 63;
            float2 bi = *(const float2*)&bias[n];
#pragma unroll
            for (int half_ = 0; half_ < 2; half_++) {
                int m = m0 + wm + mt * 16 + gr + half_ * 8;
                int bb = m >> 11, t = m & (SEQ - 1);
                float c0 = acc[mt][nt][half_ * 2 + 0] + bi.x;
                float c1 = acc[mt][nt][half_ * 2 + 1] + bi.y;
                if (z < 2) {
                    *(__half2*)&out[(((size_t)(bb * N_HEAD + h)) * SEQ + t) * 64 + d] =
                        __floats2half2_rn(c0, c1);
                } else {
                    size_t base = (((size_t)(bb * N_HEAD + h)) * 64 + d) * SEQ + t;
                    out[base] = __float2half(c0);
                    out[base + SEQ] = __float2half(c1);
                }
            }
        }
    }
}

// Proj: A = g_O fp16, B = g_Wt[3]; fp32 out + bias.
__global__ __launch_bounds__(256, 1) void proj_gemm_kernel(
    const float* __restrict__ bp, float* __restrict__ out)
{
    extern __shared__ __half smem[];
    const int m0 = blockIdx.y * 128, n0 = blockIdx.x * 256;

    float acc[4][8][4];
    gemm_fp16_main(g_O, g_Wt[3], m0, n0, smem, acc);

    const int tid = threadIdx.x;
    const int warp = tid >> 5, lane = tid & 31;
    const int wm = (warp >> 2) * 64, wn = (warp & 3) * 64;
    const int gr = lane >> 2, gc = lane & 3;

#pragma unroll
    for (int mt = 0; mt < 4; mt++) {
#pragma unroll
        for (int nt = 0; nt < 8; nt++) {
            int n = n0 + wn + nt * 8 + 2 * gc;
            float2 bi = *(const float2*)&bp[n];
#pragma unroll
            for (int half_ = 0; half_ < 2; half_++) {
                int m = m0 + wm + mt * 16 + gr + half_ * 8;
                float2 v = make_float2(acc[mt][nt][half_ * 2 + 0] + bi.x,
                                       acc[mt][nt][half_ * 2 + 1] + bi.y);
                *(float2*)&out[(size_t)m * N_EMBD + n] = v;
            }
        }
    }
}

// ---------------------------------------------------------------------------
// Fused causal attention, fp16 m16n8k16, cp.async double-buffered K/V.
// Block: (b,h,128-q tile), 8 warps, warp = 16-row strip; 32-key tiles.
// Strides (halves): Qs/Ks 72 (144B, 16B-aligned, CF), VsT/Ps 40 (CF).
// ---------------------------------------------------------------------------
#define QSH 72
#define KSH 72
#define VSH 40
#define PSH 40
#define QS_H   (128 * QSH)           // 9216
#define KS_H   (32 * KSH)            // 2304 per buffer
#define VS_H   (64 * VSH)            // 2560 per buffer
#define PS_H   (128 * PSH)           // 5120
#define ATTN_SMEM_BYTES ((QS_H + 2 * KS_H + 2 * VS_H + PS_H) * 2)  // 48128

__global__ __launch_bounds__(256) void attn_kernel()
{
    extern __shared__ __half sm[];
    __half* Qs  = sm;
    __half* Ks0 = Qs + QS_H;
    __half* Vs0 = Ks0 + 2 * KS_H;
    __half* Ps  = Vs0 + 2 * VS_H;

    const int qt = blockIdx.x;
    const int h  = blockIdx.y;
    const int b  = blockIdx.z;
    const int tid  = threadIdx.x;
    const int warp = tid >> 5, lane = tid & 31;
    const int gr = lane >> 2, gc = lane & 3;
    const int rw = warp * 16;

    const int q0 = qt * 128;
    const __half* Qg = g_Q + (((size_t)(b * N_HEAD + h)) * SEQ + q0) * 64;
    const __half* Kb = g_K + ((size_t)(b * N_HEAD + h)) * SEQ * 64;
    const __half* Vb = g_V + ((size_t)(b * N_HEAD + h)) * 64 * SEQ; // (D,T)

    const int nkt = 4 * qt + 4;

    // issue tile 0: K rows 32x64h (cp16), V rows 64x32h (cp8)
    {
        int r = tid >> 3, ch = tid & 7;
        cp16(&Ks0[r * KSH + ch * 8], Kb + r * 64 + ch * 8);
#pragma unroll
        for (int i = 0; i < 2; i++) {
            int idx = tid + i * 256;
            int vr = idx >> 3, vch = idx & 7;
            cp8(&Vs0[vr * VSH + vch * 4], Vb + (size_t)vr * SEQ + vch * 4);
        }
        CP_COMMIT();
    }

    // Q tile copy: 128 rows x 64 halves, uint4 (rows 144B -> 16B aligned)
    for (int idx = tid; idx < 1024; idx += 256) {
        int r = idx >> 3, c8 = (idx & 7) * 8;
        *(uint4*)&Qs[r * QSH + c8] = *(const uint4*)&Qg[r * 64 + c8];
    }

    float m_[2] = {-1e30f, -1e30f};
    float l_[2] = {0.f, 0.f};
    float o[8][4];
#pragma unroll
    for (int dt = 0; dt < 8; dt++)
#pragma unroll
        for (int j = 0; j < 4; j++) o[dt][j] = 0.f;

    const int row0 = q0 + rw + gr;
    const int row1 = row0 + 8;
    const int wrow_max = q0 + rw + 15;

    for (int kb = 0; kb < nkt; kb++) {
        const bool has_next = (kb + 1) < nkt;
        __syncthreads();
        if (has_next) {
            const __half* Kg = Kb + (size_t)(kb + 1) * 32 * 64;
            const __half* Vg = Vb + (size_t)(kb + 1) * 32;    // t offset
            __half* Kd = Ks0 + ((kb + 1) & 1) * KS_H;
            __half* Vd = Vs0 + ((kb + 1) & 1) * VS_H;
            int r = tid >> 3, ch = tid & 7;
            cp16(&Kd[r * KSH + ch * 8], Kg + r * 64 + ch * 8);
#pragma unroll
            for (int i = 0; i < 2; i++) {
                int idx = tid + i * 256;
                int vr = idx >> 3, vch = idx & 7;
                cp8(&Vd[vr * VSH + vch * 4], Vg + (size_t)vr * SEQ + vch * 4);
            }
            CP_COMMIT();
            CP_WAIT(1);
        } else {
            CP_WAIT(0);
        }
        __syncthreads();

        if (kb * 32 > wrow_max) continue;

        const __half* Kt = Ks0 + (kb & 1) * KS_H;
        const __half* Vt = Vs0 + (kb & 1) * VS_H;

        // S = Q K^T (16 x 32), k = 64 in 4 chunks of 16
        float s[4][4];
#pragma unroll
        for (int nt = 0; nt < 4; nt++)
#pragma unroll
            for (int j = 0; j < 4; j++) s[nt][j] = 0.f;

#pragma unroll
        for (int ch = 0; ch < 4; ch++) {
            int k = ch * 16;
            const __half* q = Qs + (rw + gr) * QSH + k + 2 * gc;
            unsigned af[4];
            af[0] = *(const unsigned*)q;
            af[1] = *(const unsigned*)(q + 8 * QSH);
            af[2] = *(const unsigned*)(q + 8);
            af[3] = *(const unsigned*)(q + 8 * QSH + 8);
#pragma unroll
            for (int nt = 0; nt < 4; nt++) {
                const __half* kp = Kt + (nt * 8 + gr) * KSH + k + 2 * gc;
                unsigned bf[2];
                bf[0] = *(const unsigned*)kp;
                bf[1] = *(const unsigned*)(kp + 8);
                mma_fp16(s[nt], af, bf);
            }
        }

        // scale + causal mask
#pragma unroll
        for (int nt = 0; nt < 4; nt++) {
            int c0 = kb * 32 + nt * 8 + 2 * gc;
            s[nt][0] = (c0     > row0) ? -1e30f : s[nt][0] * 0.125f;
            s[nt][1] = (c0 + 1 > row0) ? -1e30f : s[nt][1] * 0.125f;
            s[nt][2] = (c0     > row1) ? -1e30f : s[nt][2] * 0.125f;
            s[nt][3] = (c0 + 1 > row1) ? -1e30f : s[nt][3] * 0.125f;
        }

        // online softmax (4-lane groups own rows)
        float mx0 = -1e30f, mx1 = -1e30f;
#pragma unroll
        for (int nt = 0; nt < 4; nt++) {
            mx0 = fmaxf(mx0, fmaxf(s[nt][0], s[nt][1]));
            mx1 = fmaxf(mx1, fmaxf(s[nt][2], s[nt][3]));
        }
#pragma unroll
        for (int off = 1; off < 4; off <<= 1) {
            mx0 = fmaxf(mx0, __shfl_xor_sync(0xffffffffu, mx0, off));
            mx1 = fmaxf(mx1, __shfl_xor_sync(0xffffffffu, mx1, off));
        }
        float mn0 = fmaxf(m_[0], mx0), mn1 = fmaxf(m_[1], mx1);
        float sc0 = __expf(m_[0] - mn0), sc1 = __expf(m_[1] - mn1);
        float sum0 = 0.f, sum1 = 0.f;
#pragma unroll
        for (int nt = 0; nt < 4; nt++) {
            s[nt][0] = __expf(s[nt][0] - mn0);
            s[nt][1] = __expf(s[nt][1] - mn0);
            s[nt][2] = __expf(s[nt][2] - mn1);
            s[nt][3] = __expf(s[nt][3] - mn1);
            sum0 += s[nt][0] + s[nt][1];
            sum1 += s[nt][2] + s[nt][3];
        }
#pragma unroll
        for (int off = 1; off < 4; off <<= 1) {
            sum0 += __shfl_xor_sync(0xffffffffu, sum0, off);
            sum1 += __shfl_xor_sync(0xffffffffu, sum1, off);
        }
        l_[0] = l_[0] * sc0 + sum0;
        l_[1] = l_[1] * sc1 + sum1;
        m_[0] = mn0;
        m_[1] = mn1;
#pragma unroll
        for (int dt = 0; dt < 8; dt++) {
            o[dt][0] *= sc0; o[dt][1] *= sc0;
            o[dt][2] *= sc1; o[dt][3] *= sc1;
        }

        // publish P fp16 into warp-private Ps strip
#pragma unroll
        for (int nt = 0; nt < 4; nt++) {
            int c = nt * 8 + 2 * gc;
            *(__half2*)&Ps[(rw + gr) * PSH + c]     = __floats2half2_rn(s[nt][0], s[nt][1]);
            *(__half2*)&Ps[(rw + gr + 8) * PSH + c] = __floats2half2_rn(s[nt][2], s[nt][3]);
        }
        __syncwarp();

        // O += P @ V  (P 16x32, V 32x64), 2 chunks of k16
#pragma unroll
        for (int ch = 0; ch < 2; ch++) {
            int ss = ch * 16;
            const __half* pp = Ps + (rw + gr) * PSH + ss + 2 * gc;
            unsigned pa[4];
            pa[0] = *(const unsigned*)pp;
            pa[1] = *(const unsigned*)(pp + 8 * PSH);
            pa[2] = *(const unsigned*)(pp + 8);
            pa[3] = *(const unsigned*)(pp + 8 * PSH + 8);
#pragma unroll
            for (int dt = 0; dt < 8; dt++) {
                const __half* vp = Vt + (dt * 8 + gr) * VSH + ss + 2 * gc;
                unsigned bf[2];
                bf[0] = *(const unsigned*)vp;
                bf[1] = *(const unsigned*)(vp + 8);
                mma_fp16(o[dt], pa, bf);
            }
        }
    }

    // normalize + store fp16 to g_O (B,T,C)
    float inv0 = 1.f / l_[0];
    float inv1 = 1.f / l_[1];
#pragma unroll
    for (int dt = 0; dt < 8; dt++) {
        int col = h * 64 + dt * 8 + 2 * gc;
        *(__half2*)&g_O[((size_t)b * SEQ + row0) * N_EMBD + col] =
            __floats2half2_rn(o[dt][0] * inv0, o[dt][1] * inv0);
        *(__half2*)&g_O[((size_t)b * SEQ + row1) * N_EMBD + col] =
            __floats2half2_rn(o[dt][2] * inv1, o[dt][3] * inv1);
    }
}

// ---------------------------------------------------------------------------
extern "C" void kernel_launch(void* const* d_in, const int* in_sizes, int n_in,
                              void* d_out, int out_size)
{
    const float* x  = (const float*)d_in[0];
    const float* Wq = (const float*)d_in[1];
    const float* bq = (const float*)d_in[2];
    const float* Wk = (const float*)d_in[3];
    const float* bk = (const float*)d_in[4];
    const float* Wv = (const float*)d_in[5];
    const float* bv = (const float*)d_in[6];
    const float* Wp = (const float*)d_in[7];
    const float* bp = (const float*)d_in[8];
    float* out = (float*)d_out;

    cudaFuncSetAttribute(qkv_gemm_kernel,
                         cudaFuncAttributeMaxDynamicSharedMemorySize,
                         GEMM_SMEM_BYTES);
    cudaFuncSetAttribute(proj_gemm_kernel,
                         cudaFuncAttributeMaxDynamicSharedMemorySize,
                         GEMM_SMEM_BYTES);
    cudaFuncSetAttribute(attn_kernel,
                         cudaFuncAttributeMaxDynamicSharedMemorySize,
                         ATTN_SMEM_BYTES);

    prep_x_kernel<<<M_TOT * N_EMBD / 4 / 256, 256>>>(x);
    prep_w_kernel<<<dim3(32, 32, 4), dim3(32, 8)>>>(Wq, Wk, Wv, Wp);

    qkv_gemm_kernel<<<dim3(4, 64, 3), 256, GEMM_SMEM_BYTES>>>(bq, bk, bv);

    attn_kernel<<<dim3(SEQ / 128, N_HEAD, BATCH), 256, ATTN_SMEM_BYTES>>>();

    proj_gemm_kernel<<<dim3(4, 64, 1), 256, GEMM_SMEM_BYTES>>>(bp, out);
}

// round 8
// speedup vs baseline: 5.1792x; 1.0094x over previous
#include <cuda_runtime.h>
#include <cuda_fp16.h>
#include <math.h>
#include <stdint.h>

#define N_EMBD   1024
#define N_HEAD   16
#define HEAD_DIM 64
#define BATCH    4
#define SEQ      2048
#define M_TOT    8192

// ---------------------------------------------------------------------------
// Device scratch (fp16). V stored transposed (B,H,D,T); Q,K as (B,H,T,D).
// ---------------------------------------------------------------------------
__device__ __half g_X[(size_t)M_TOT * N_EMBD];
__device__ __half g_Wt[4][(size_t)N_EMBD * N_EMBD];   // W^T [n][k]
__device__ __half g_Q[(size_t)BATCH * N_HEAD * SEQ * HEAD_DIM];
__device__ __half g_K[(size_t)BATCH * N_HEAD * SEQ * HEAD_DIM];
__device__ __half g_V[(size_t)BATCH * N_HEAD * HEAD_DIM * SEQ]; // (B,H,D,T)
__device__ __half g_O[(size_t)M_TOT * N_EMBD];        // attn out (B,T,C)

// ---------------------------------------------------------------------------
__device__ __forceinline__ void mma_fp16(float* d, const unsigned* a,
                                         const unsigned* b) {
    asm volatile(
        "mma.sync.aligned.m16n8k16.row.col.f32.f16.f16.f32 "
        "{%0,%1,%2,%3}, {%4,%5,%6,%7}, {%8,%9}, {%0,%1,%2,%3};"
        : "+f"(d[0]), "+f"(d[1]), "+f"(d[2]), "+f"(d[3])
        : "r"(a[0]), "r"(a[1]), "r"(a[2]), "r"(a[3]), "r"(b[0]), "r"(b[1]));
}

__device__ __forceinline__ void cp16(void* smem_dst, const void* gsrc) {
    unsigned u = (unsigned)__cvta_generic_to_shared(smem_dst);
    asm volatile("cp.async.cg.shared.global [%0], [%1], 16;\n"
                 :: "r"(u), "l"(gsrc));
}
__device__ __forceinline__ void cp8(void* smem_dst, const void* gsrc) {
    unsigned u = (unsigned)__cvta_generic_to_shared(smem_dst);
    asm volatile("cp.async.ca.shared.global [%0], [%1], 8;\n"
                 :: "r"(u), "l"(gsrc));
}
#define CP_COMMIT() asm volatile("cp.async.commit_group;\n" ::: "memory")
#define CP_WAIT(N)  asm volatile("cp.async.wait_group %0;\n" :: "n"(N) : "memory")

__device__ __forceinline__ unsigned h2u(__half2 h) {
    return *(unsigned*)&h;
}

// ---------------------------------------------------------------------------
// prep kernels
// ---------------------------------------------------------------------------
__global__ void prep_x_kernel(const float* __restrict__ x) {
    size_t i = (size_t)blockIdx.x * 256 + threadIdx.x;   // per 4 floats
    float4 v = ((const float4*)x)[i];
    uint2 u;
    u.x = h2u(__floats2half2_rn(v.x, v.y));
    u.y = h2u(__floats2half2_rn(v.z, v.w));
    ((uint2*)g_X)[i] = u;
}

__global__ void prep_w_kernel(const float* __restrict__ Wq,
                              const float* __restrict__ Wk,
                              const float* __restrict__ Wv,
                              const float* __restrict__ Wp) {
    __shared__ float tile[32][33];
    int z = blockIdx.z;
    const float* W = (z == 0) ? Wq : (z == 1) ? Wk : (z == 2) ? Wv : Wp;
    int x0 = blockIdx.x * 32;   // n
    int y0 = blockIdx.y * 32;   // k
    int tx = threadIdx.x;
    for (int i = threadIdx.y; i < 32; i += 8)
        tile[i][tx] = W[(size_t)(y0 + i) * N_EMBD + x0 + tx];
    __syncthreads();
    for (int i = threadIdx.y; i < 32; i += 8)
        g_Wt[z][(size_t)(x0 + i) * N_EMBD + y0 + tx] = __float2half(tile[tx][i]);
}

// ---------------------------------------------------------------------------
// fp16 GEMM: block 128(M) x 256(N), 8 warps (2x4) of 64x64, BK=32,
// cp.async double-buffered. Strides in halves: 40 (word-stride 20 -> CF).
// smem halves: As[2][128*40]=10240, Bs[2][256*40]=20480 -> 61440 bytes.
// ---------------------------------------------------------------------------
#define GSTR 40
#define AS_OFF(buf) ((buf) * 5120)
#define BS_OFF(buf) (10240 + (buf) * 10240)
#define GEMM_SMEM_BYTES 61440

__device__ __forceinline__ void gemm_load_stage(
    const __half* __restrict__ A, const __half* __restrict__ Bt,
    int m0, int n0, int kb, __half* smem, int buf, int tid)
{
    const int k0 = kb * 32;
#pragma unroll
    for (int i = 0; i < 4; i++) {
        int idx = tid + i * 256;
        int r = idx >> 3, ch = idx & 7;
        cp8(smem + AS_OFF(buf) + r * GSTR + ch * 4,
            A + (size_t)(m0 + r) * N_EMBD + k0 + ch * 4);
    }
#pragma unroll
    for (int i = 0; i < 8; i++) {
        int idx = tid + i * 256;
        int r = idx >> 3, ch = idx & 7;
        cp8(smem + BS_OFF(buf) + r * GSTR + ch * 4,
            Bt + (size_t)(n0 + r) * N_EMBD + k0 + ch * 4);
    }
}

__device__ __forceinline__ void gemm_fp16_main(
    const __half* __restrict__ A, const __half* __restrict__ Bt,
    int m0, int n0, __half* smem, float acc[4][8][4])
{
    const int tid = threadIdx.x;
    const int warp = tid >> 5, lane = tid & 31;
    const int wm = (warp >> 2) * 64;       // warpM in {0,1}
    const int wn = (warp & 3) * 64;        // warpN in {0..3}
    const int gr = lane >> 2, gc = lane & 3;

#pragma unroll
    for (int mt = 0; mt < 4; mt++)
#pragma unroll
        for (int nt = 0; nt < 8; nt++)
#pragma unroll
            for (int j = 0; j < 4; j++) acc[mt][nt][j] = 0.f;

    gemm_load_stage(A, Bt, m0, n0, 0, smem, 0, tid);
    CP_COMMIT();

    for (int kb = 0; kb < 32; kb++) {
        __syncthreads();                    // prior compute done; buf free
        if (kb + 1 < 32) {
            gemm_load_stage(A, Bt, m0, n0, kb + 1, smem, (kb + 1) & 1, tid);
            CP_COMMIT();
            CP_WAIT(1);
        } else {
            CP_WAIT(0);
        }
        __syncthreads();                    // stage kb visible

        const __half* Ab = smem + AS_OFF(kb & 1);
        const __half* Bb = smem + BS_OFF(kb & 1);
#pragma unroll
        for (int kk = 0; kk < 32; kk += 16) {
            unsigned af[4][4];
#pragma unroll
            for (int mt = 0; mt < 4; mt++) {
                const __half* p = Ab + (wm + mt * 16 + gr) * GSTR + kk + 2 * gc;
                af[mt][0] = *(const unsigned*)p;
                af[mt][1] = *(const unsigned*)(p + 8 * GSTR);
                af[mt][2] = *(const unsigned*)(p + 8);
                af[mt][3] = *(const unsigned*)(p + 8 * GSTR + 8);
            }
            unsigned bf[8][2];
#pragma unroll
            for (int nt = 0; nt < 8; nt++) {
                const __half* p = Bb + (wn + nt * 8 + gr) * GSTR + kk + 2 * gc;
                bf[nt][0] = *(const unsigned*)p;
                bf[nt][1] = *(const unsigned*)(p + 8);
            }
#pragma unroll
            for (int mt = 0; mt < 4; mt++)
#pragma unroll
                for (int nt = 0; nt < 8; nt++)
                    mma_fp16(acc[mt][nt], af[mt], bf[nt]);
        }
    }
}

// QKV: out Q/K (B,H,T,D) half; V (B,H,D,T) half. +bias.
__global__ __launch_bounds__(256, 1) void qkv_gemm_kernel(
    const float* __restrict__ bq, const float* __restrict__ bk,
    const float* __restrict__ bv)
{
    extern __shared__ __half smem[];
    const int z = blockIdx.z;
    const float* bias = (z == 0) ? bq : (z == 1) ? bk : bv;
    __half* out = (z == 0) ? g_Q : (z == 1) ? g_K : g_V;
    const int m0 = blockIdx.y * 128, n0 = blockIdx.x * 256;

    float acc[4][8][4];
    gemm_fp16_main(g_X, g_Wt[z], m0, n0, smem, acc);

    const int tid = threadIdx.x;
    const int warp = tid >> 5, lane = tid & 31;
    const int wm = (warp >> 2) * 64, wn = (warp & 3) * 64;
    const int gr = lane >> 2, gc = lane & 3;

#pragma unroll
    for (int mt = 0; mt < 4; mt++) {
#pragma unroll
        for (int nt = 0; nt < 8; nt++) {
            int n = n0 + wn + nt * 8 + 2 * gc;
            int h = n >> 6, d = n & 63;
            float2 bi = *(const float2*)&bias[n];
#pragma unroll
            for (int half_ = 0; half_ < 2; half_++) {
                int m = m0 + wm + mt * 16 + gr + half_ * 8;
                int bb = m >> 11, t = m & (SEQ - 1);
                float c0 = acc[mt][nt][half_ * 2 + 0] + bi.x;
                float c1 = acc[mt][nt][half_ * 2 + 1] + bi.y;
                if (z < 2) {
                    *(__half2*)&out[(((size_t)(bb * N_HEAD + h)) * SEQ + t) * 64 + d] =
                        __floats2half2_rn(c0, c1);
                } else {
                    size_t base = (((size_t)(bb * N_HEAD + h)) * 64 + d) * SEQ + t;
                    out[base] = __float2half(c0);
                    out[base + SEQ] = __float2half(c1);
                }
            }
        }
    }
}

// Proj: A = g_O fp16, B = g_Wt[3]; fp32 out + bias.
__global__ __launch_bounds__(256, 1) void proj_gemm_kernel(
    const float* __restrict__ bp, float* __restrict__ out)
{
    extern __shared__ __half smem[];
    const int m0 = blockIdx.y * 128, n0 = blockIdx.x * 256;

    float acc[4][8][4];
    gemm_fp16_main(g_O, g_Wt[3], m0, n0, smem, acc);

    const int tid = threadIdx.x;
    const int warp = tid >> 5, lane = tid & 31;
    const int wm = (warp >> 2) * 64, wn = (warp & 3) * 64;
    const int gr = lane >> 2, gc = lane & 3;

#pragma unroll
    for (int mt = 0; mt < 4; mt++) {
#pragma unroll
        for (int nt = 0; nt < 8; nt++) {
            int n = n0 + wn + nt * 8 + 2 * gc;
            float2 bi = *(const float2*)&bp[n];
#pragma unroll
            for (int half_ = 0; half_ < 2; half_++) {
                int m = m0 + wm + mt * 16 + gr + half_ * 8;
                float2 v = make_float2(acc[mt][nt][half_ * 2 + 0] + bi.x,
                                       acc[mt][nt][half_ * 2 + 1] + bi.y);
                *(float2*)&out[(size_t)m * N_EMBD + n] = v;
            }
        }
    }
}

// ---------------------------------------------------------------------------
// Fused causal attention, fp16 m16n8k16, cp.async double-buffered K/V.
// EXACT R5 data path (32-key tiles, scalar fragments, V^T smem) wrapped in a
// 2-pass causal-pairing loop: block px does q-tiles {15-px, px} -> every
// block processes exactly 68 key-tiles.
// ---------------------------------------------------------------------------
#define QSH 72
#define KSH 72
#define VSH 40
#define PSH 40
#define QS_H   (128 * QSH)           // 9216
#define KS_H   (32 * KSH)            // 2304 per buffer
#define VS_H   (64 * VSH)            // 2560 per buffer ([d=64][t=32])
#define PS_H   (128 * PSH)           // 5120
#define ATTN_SMEM_BYTES ((QS_H + 2 * KS_H + 2 * VS_H + PS_H) * 2)

__global__ __launch_bounds__(256) void attn_kernel()
{
    extern __shared__ __half sm[];
    __half* Qs  = sm;
    __half* Ks0 = Qs + QS_H;
    __half* Vs0 = Ks0 + 2 * KS_H;
    __half* Ps  = Vs0 + 2 * VS_H;

    const int px = blockIdx.x;          // 0..7
    const int h  = blockIdx.y;
    const int b  = blockIdx.z;
    const int tid  = threadIdx.x;
    const int warp = tid >> 5, lane = tid & 31;
    const int gr = lane >> 2, gc = lane & 3;
    const int rw = warp * 16;

    const __half* Kb = g_K + ((size_t)(b * N_HEAD + h)) * SEQ * 64;
    const __half* Vb = g_V + ((size_t)(b * N_HEAD + h)) * 64 * SEQ; // (D,T)

    for (int pass = 0; pass < 2; pass++) {
        const int qt = pass ? px : (15 - px);
        const int q0 = qt * 128;
        const int nkt = 4 * qt + 4;       // 32-key tiles needed

        const __half* Qg = g_Q + (((size_t)(b * N_HEAD + h)) * SEQ + q0) * 64;

        // issue tile 0: K rows 32x64h (cp16), V rows 64x32h (cp8)
        {
            int r = tid >> 3, ch = tid & 7;
            cp16(&Ks0[r * KSH + ch * 8], Kb + r * 64 + ch * 8);
#pragma unroll
            for (int i = 0; i < 2; i++) {
                int idx = tid + i * 256;
                int vr = idx >> 3, vch = idx & 7;
                cp8(&Vs0[vr * VSH + vch * 4], Vb + (size_t)vr * SEQ + vch * 4);
            }
            CP_COMMIT();
        }

        // Q tile copy: 128 rows x 64 halves, uint4
        for (int idx = tid; idx < 1024; idx += 256) {
            int r = idx >> 3, c8 = (idx & 7) * 8;
            *(uint4*)&Qs[r * QSH + c8] = *(const uint4*)&Qg[r * 64 + c8];
        }

        float m_[2] = {-1e30f, -1e30f};
        float l_[2] = {0.f, 0.f};
        float o[8][4];
#pragma unroll
        for (int dt = 0; dt < 8; dt++)
#pragma unroll
            for (int j = 0; j < 4; j++) o[dt][j] = 0.f;

        const int row0 = q0 + rw + gr;
        const int row1 = row0 + 8;
        const int wrow_max = q0 + rw + 15;

        for (int kb = 0; kb < nkt; kb++) {
            const bool has_next = (kb + 1) < nkt;
            __syncthreads();
            if (has_next) {
                const __half* Kg = Kb + (size_t)(kb + 1) * 32 * 64;
                const __half* Vg = Vb + (size_t)(kb + 1) * 32;    // t offset
                __half* Kd = Ks0 + ((kb + 1) & 1) * KS_H;
                __half* Vd = Vs0 + ((kb + 1) & 1) * VS_H;
                int r = tid >> 3, ch = tid & 7;
                cp16(&Kd[r * KSH + ch * 8], Kg + r * 64 + ch * 8);
#pragma unroll
                for (int i = 0; i < 2; i++) {
                    int idx = tid + i * 256;
                    int vr = idx >> 3, vch = idx & 7;
                    cp8(&Vd[vr * VSH + vch * 4], Vg + (size_t)vr * SEQ + vch * 4);
                }
                CP_COMMIT();
                CP_WAIT(1);
            } else {
                CP_WAIT(0);
            }
            __syncthreads();

            if (kb * 32 > wrow_max) continue;

            const __half* Kt = Ks0 + (kb & 1) * KS_H;
            const __half* Vt = Vs0 + (kb & 1) * VS_H;

            // S = Q K^T (16 x 32), k = 64 in 4 chunks of 16
            float s[4][4];
#pragma unroll
            for (int nt = 0; nt < 4; nt++)
#pragma unroll
                for (int j = 0; j < 4; j++) s[nt][j] = 0.f;

#pragma unroll
            for (int ch = 0; ch < 4; ch++) {
                int k = ch * 16;
                const __half* q = Qs + (rw + gr) * QSH + k + 2 * gc;
                unsigned af[4];
                af[0] = *(const unsigned*)q;
                af[1] = *(const unsigned*)(q + 8 * QSH);
                af[2] = *(const unsigned*)(q + 8);
                af[3] = *(const unsigned*)(q + 8 * QSH + 8);
#pragma unroll
                for (int nt = 0; nt < 4; nt++) {
                    const __half* kp = Kt + (nt * 8 + gr) * KSH + k + 2 * gc;
                    unsigned bf[2];
                    bf[0] = *(const unsigned*)kp;
                    bf[1] = *(const unsigned*)(kp + 8);
                    mma_fp16(s[nt], af, bf);
                }
            }

            // scale + causal mask
#pragma unroll
            for (int nt = 0; nt < 4; nt++) {
                int c0 = kb * 32 + nt * 8 + 2 * gc;
                s[nt][0] = (c0     > row0) ? -1e30f : s[nt][0] * 0.125f;
                s[nt][1] = (c0 + 1 > row0) ? -1e30f : s[nt][1] * 0.125f;
                s[nt][2] = (c0     > row1) ? -1e30f : s[nt][2] * 0.125f;
                s[nt][3] = (c0 + 1 > row1) ? -1e30f : s[nt][3] * 0.125f;
            }

            // online softmax (4-lane groups own rows)
            float mx0 = -1e30f, mx1 = -1e30f;
#pragma unroll
            for (int nt = 0; nt < 4; nt++) {
                mx0 = fmaxf(mx0, fmaxf(s[nt][0], s[nt][1]));
                mx1 = fmaxf(mx1, fmaxf(s[nt][2], s[nt][3]));
            }
#pragma unroll
            for (int off = 1; off < 4; off <<= 1) {
                mx0 = fmaxf(mx0, __shfl_xor_sync(0xffffffffu, mx0, off));
                mx1 = fmaxf(mx1, __shfl_xor_sync(0xffffffffu, mx1, off));
            }
            float mn0 = fmaxf(m_[0], mx0), mn1 = fmaxf(m_[1], mx1);
            float sc0 = __expf(m_[0] - mn0), sc1 = __expf(m_[1] - mn1);
            float sum0 = 0.f, sum1 = 0.f;
#pragma unroll
            for (int nt = 0; nt < 4; nt++) {
                s[nt][0] = __expf(s[nt][0] - mn0);
                s[nt][1] = __expf(s[nt][1] - mn0);
                s[nt][2] = __expf(s[nt][2] - mn1);
                s[nt][3] = __expf(s[nt][3] - mn1);
                sum0 += s[nt][0] + s[nt][1];
                sum1 += s[nt][2] + s[nt][3];
            }
#pragma unroll
            for (int off = 1; off < 4; off <<= 1) {
                sum0 += __shfl_xor_sync(0xffffffffu, sum0, off);
                sum1 += __shfl_xor_sync(0xffffffffu, sum1, off);
            }
            l_[0] = l_[0] * sc0 + sum0;
            l_[1] = l_[1] * sc1 + sum1;
            m_[0] = mn0;
            m_[1] = mn1;
#pragma unroll
            for (int dt = 0; dt < 8; dt++) {
                o[dt][0] *= sc0; o[dt][1] *= sc0;
                o[dt][2] *= sc1; o[dt][3] *= sc1;
            }

            // publish P fp16 into warp-private Ps strip
#pragma unroll
            for (int nt = 0; nt < 4; nt++) {
                int c = nt * 8 + 2 * gc;
                *(__half2*)&Ps[(rw + gr) * PSH + c]     = __floats2half2_rn(s[nt][0], s[nt][1]);
                *(__half2*)&Ps[(rw + gr + 8) * PSH + c] = __floats2half2_rn(s[nt][2], s[nt][3]);
            }
            __syncwarp();

            // O += P @ V  (P 16x32, V^T smem [d][t]), 2 chunks of k16
#pragma unroll
            for (int ch = 0; ch < 2; ch++) {
                int ss = ch * 16;
                const __half* pp = Ps + (rw + gr) * PSH + ss + 2 * gc;
                unsigned pa[4];
                pa[0] = *(const unsigned*)pp;
                pa[1] = *(const unsigned*)(pp + 8 * PSH);
                pa[2] = *(const unsigned*)(pp + 8);
                pa[3] = *(const unsigned*)(pp + 8 * PSH + 8);
#pragma unroll
                for (int dt = 0; dt < 8; dt++) {
                    const __half* vp = Vt + (dt * 8 + gr) * VSH + ss + 2 * gc;
                    unsigned bf[2];
                    bf[0] = *(const unsigned*)vp;
                    bf[1] = *(const unsigned*)(vp + 8);
                    mma_fp16(o[dt], pa, bf);
                }
            }
        }

        // normalize + store fp16 to g_O (B,T,C)
        float inv0 = 1.f / l_[0];
        float inv1 = 1.f / l_[1];
#pragma unroll
        for (int dt = 0; dt < 8; dt++) {
            int col = h * 64 + dt * 8 + 2 * gc;
            *(__half2*)&g_O[((size_t)b * SEQ + row0) * N_EMBD + col] =
                __floats2half2_rn(o[dt][0] * inv0, o[dt][1] * inv0);
            *(__half2*)&g_O[((size_t)b * SEQ + row1) * N_EMBD + col] =
                __floats2half2_rn(o[dt][2] * inv1, o[dt][3] * inv1);
        }
        __syncthreads();   // smem reuse safety before next pass prologue
    }
}

// ---------------------------------------------------------------------------
extern "C" void kernel_launch(void* const* d_in, const int* in_sizes, int n_in,
                              void* d_out, int out_size)
{
    const float* x  = (const float*)d_in[0];
    const float* Wq = (const float*)d_in[1];
    const float* bq = (const float*)d_in[2];
    const float* Wk = (const float*)d_in[3];
    const float* bk = (const float*)d_in[4];
    const float* Wv = (const float*)d_in[5];
    const float* bv = (const float*)d_in[6];
    const float* Wp = (const float*)d_in[7];
    const float* bp = (const float*)d_in[8];
    float* out = (float*)d_out;

    cudaFuncSetAttribute(qkv_gemm_kernel,
                         cudaFuncAttributeMaxDynamicSharedMemorySize,
                         GEMM_SMEM_BYTES);
    cudaFuncSetAttribute(proj_gemm_kernel,
                         cudaFuncAttributeMaxDynamicSharedMemorySize,
                         GEMM_SMEM_BYTES);
    cudaFuncSetAttribute(attn_kernel,
                         cudaFuncAttributeMaxDynamicSharedMemorySize,
                         ATTN_SMEM_BYTES);

    prep_x_kernel<<<M_TOT * N_EMBD / 4 / 256, 256>>>(x);
    prep_w_kernel<<<dim3(32, 32, 4), dim3(32, 8)>>>(Wq, Wk, Wv, Wp);

    qkv_gemm_kernel<<<dim3(4, 64, 3), 256, GEMM_SMEM_BYTES>>>(bq, bk, bv);

    attn_kernel<<<dim3(8, N_HEAD, BATCH), 256, ATTN_SMEM_BYTES>>>();

    proj_gemm_kernel<<<dim3(4, 64, 1), 256, GEMM_SMEM_BYTES>>>(bp, out);
}

// round 9
// speedup vs baseline: 6.0507x; 1.1683x over previous
#include <cuda_runtime.h>
#include <cuda_fp16.h>
#include <math.h>
#include <stdint.h>

#define N_EMBD   1024
#define N_HEAD   16
#define HEAD_DIM 64
#define BATCH    4
#define SEQ      2048
#define M_TOT    8192

// ---------------------------------------------------------------------------
// Device scratch (fp16). Q,K,V all (B,H,T,D); O (B,T,C). Q pre-scaled 1/8.
// ---------------------------------------------------------------------------
__device__ __half g_X[(size_t)M_TOT * N_EMBD];
__device__ __half g_Wt[4][(size_t)N_EMBD * N_EMBD];   // W^T [n][k]
__device__ __half g_Q[(size_t)BATCH * N_HEAD * SEQ * HEAD_DIM];
__device__ __half g_K[(size_t)BATCH * N_HEAD * SEQ * HEAD_DIM];
__device__ __half g_V[(size_t)BATCH * N_HEAD * SEQ * HEAD_DIM];
__device__ __half g_O[(size_t)M_TOT * N_EMBD];

// ---------------------------------------------------------------------------
__device__ __forceinline__ void mma_fp16(float* d, const unsigned* a,
                                         const unsigned* b) {
    asm volatile(
        "mma.sync.aligned.m16n8k16.row.col.f32.f16.f16.f32 "
        "{%0,%1,%2,%3}, {%4,%5,%6,%7}, {%8,%9}, {%0,%1,%2,%3};"
        : "+f"(d[0]), "+f"(d[1]), "+f"(d[2]), "+f"(d[3])
        : "r"(a[0]), "r"(a[1]), "r"(a[2]), "r"(a[3]), "r"(b[0]), "r"(b[1]));
}

__device__ __forceinline__ void ldm_x4(unsigned* r, uint32_t a) {
    asm volatile("ldmatrix.sync.aligned.m8n8.x4.shared.b16 {%0,%1,%2,%3}, [%4];"
                 : "=r"(r[0]), "=r"(r[1]), "=r"(r[2]), "=r"(r[3]) : "r"(a));
}
__device__ __forceinline__ void ldm_x4t(unsigned* r, uint32_t a) {
    asm volatile("ldmatrix.sync.aligned.m8n8.x4.trans.shared.b16 {%0,%1,%2,%3}, [%4];"
                 : "=r"(r[0]), "=r"(r[1]), "=r"(r[2]), "=r"(r[3]) : "r"(a));
}

__device__ __forceinline__ void cp16(void* smem_dst, const void* gsrc) {
    unsigned u = (unsigned)__cvta_generic_to_shared(smem_dst);
    asm volatile("cp.async.cg.shared.global [%0], [%1], 16;\n"
                 :: "r"(u), "l"(gsrc));
}
#define CP_COMMIT() asm volatile("cp.async.commit_group;\n" ::: "memory")
#define CP_WAIT(N)  asm volatile("cp.async.wait_group %0;\n" :: "n"(N) : "memory")

__device__ __forceinline__ uint32_t smem_u32(const void* p) {
    return (uint32_t)__cvta_generic_to_shared(p);
}
__device__ __forceinline__ unsigned h2u(__half2 h) { return *(unsigned*)&h; }

// ---------------------------------------------------------------------------
// prep kernels
// ---------------------------------------------------------------------------
__global__ void prep_x_kernel(const float* __restrict__ x) {
    size_t i = (size_t)blockIdx.x * 256 + threadIdx.x;
    float4 v = ((const float4*)x)[i];
    uint2 u;
    u.x = h2u(__floats2half2_rn(v.x, v.y));
    u.y = h2u(__floats2half2_rn(v.z, v.w));
    ((uint2*)g_X)[i] = u;
}

__global__ void prep_w_kernel(const float* __restrict__ Wq,
                              const float* __restrict__ Wk,
                              const float* __restrict__ Wv,
                              const float* __restrict__ Wp) {
    __shared__ float tile[32][33];
    int z = blockIdx.z;
    const float* W = (z == 0) ? Wq : (z == 1) ? Wk : (z == 2) ? Wv : Wp;
    int x0 = blockIdx.x * 32;
    int y0 = blockIdx.y * 32;
    int tx = threadIdx.x;
    for (int i = threadIdx.y; i < 32; i += 8)
        tile[i][tx] = W[(size_t)(y0 + i) * N_EMBD + x0 + tx];
    __syncthreads();
    for (int i = threadIdx.y; i < 32; i += 8)
        g_Wt[z][(size_t)(x0 + i) * N_EMBD + y0 + tx] = __float2half(tile[tx][i]);
}

// ---------------------------------------------------------------------------
// fp16 GEMM (ldmatrix): block 128x256, 8 warps (2x4) of 64x64, BK=32,
// cp.async double-buffered. Stride 40 halves. FIXED load stage: each 64-byte
// row is covered by 4 cp16 at half-offsets {0,8,16,24}.
// ---------------------------------------------------------------------------
#define GSTR 40
#define AS_OFF(buf) ((buf) * 5120)
#define BS_OFF(buf) (10240 + (buf) * 10240)
#define GEMM_SMEM_BYTES 61440

__device__ __forceinline__ void gemm_load_stage(
    const __half* __restrict__ A, const __half* __restrict__ Bt,
    int m0, int n0, int kb, __half* smem, int buf, int tid)
{
    const int k0 = kb * 32;
    // A: 128 rows x 32 halves (64B) -> 512 cp16
#pragma unroll
    for (int i = 0; i < 2; i++) {
        int idx = tid + i * 256;
        int r = idx >> 2, ch = idx & 3;
        cp16(smem + AS_OFF(buf) + r * GSTR + ch * 8,
             A + (size_t)(m0 + r) * N_EMBD + k0 + ch * 8);
    }
    // B: 256 rows -> 1024 cp16
#pragma unroll
    for (int i = 0; i < 4; i++) {
        int idx = tid + i * 256;
        int r = idx >> 2, ch = idx & 3;
        cp16(smem + BS_OFF(buf) + r * GSTR + ch * 8,
             Bt + (size_t)(n0 + r) * N_EMBD + k0 + ch * 8);
    }
}

__device__ __forceinline__ void gemm_fp16_main(
    const __half* __restrict__ A, const __half* __restrict__ Bt,
    int m0, int n0, __half* smem, float acc[4][8][4])
{
    const int tid = threadIdx.x;
    const int warp = tid >> 5, lane = tid & 31;
    const int wm = (warp >> 2) * 64;
    const int wn = (warp & 3) * 64;
    const uint32_t sb = smem_u32(smem);
    const int a_lane = ((lane & 15) + wm) * GSTR + (lane >> 4) * 8;
    const int b_lane = ((lane >> 4) * 8 + (lane & 7) + wn) * GSTR +
                       ((lane >> 3) & 1) * 8;

#pragma unroll
    for (int mt = 0; mt < 4; mt++)
#pragma unroll
        for (int nt = 0; nt < 8; nt++)
#pragma unroll
            for (int j = 0; j < 4; j++) acc[mt][nt][j] = 0.f;

    gemm_load_stage(A, Bt, m0, n0, 0, smem, 0, tid);
    CP_COMMIT();

    for (int kb = 0; kb < 32; kb++) {
        __syncthreads();
        if (kb + 1 < 32) {
            gemm_load_stage(A, Bt, m0, n0, kb + 1, smem, (kb + 1) & 1, tid);
            CP_COMMIT();
            CP_WAIT(1);
        } else {
            CP_WAIT(0);
        }
        __syncthreads();

        const uint32_t Ab = sb + 2 * (AS_OFF(kb & 1) + a_lane);
        const uint32_t Bb = sb + 2 * (BS_OFF(kb & 1) + b_lane);
#pragma unroll
        for (int kk = 0; kk < 32; kk += 16) {
            unsigned af[4][4];
#pragma unroll
            for (int mt = 0; mt < 4; mt++)
                ldm_x4(af[mt], Ab + 2 * (mt * 16 * GSTR + kk));
            unsigned bf[8][2];
#pragma unroll
            for (int ntp = 0; ntp < 4; ntp++) {
                unsigned r[4];
                ldm_x4(r, Bb + 2 * (ntp * 16 * GSTR + kk));
                bf[2 * ntp][0] = r[0]; bf[2 * ntp][1] = r[1];
                bf[2 * ntp + 1][0] = r[2]; bf[2 * ntp + 1][1] = r[3];
            }
#pragma unroll
            for (int mt = 0; mt < 4; mt++)
#pragma unroll
                for (int nt = 0; nt < 8; nt++)
                    mma_fp16(acc[mt][nt], af[mt], bf[nt]);
        }
    }
}

// QKV: out (B,H,T,D) fp16, +bias; Q pre-scaled by 1/8.
__global__ __launch_bounds__(256, 1) void qkv_gemm_kernel(
    const float* __restrict__ bq, const float* __restrict__ bk,
    const float* __restrict__ bv)
{
    extern __shared__ __half smem[];
    const int z = blockIdx.z;
    const float* bias = (z == 0) ? bq : (z == 1) ? bk : bv;
    __half* out = (z == 0) ? g_Q : (z == 1) ? g_K : g_V;
    const float oscale = (z == 0) ? 0.125f : 1.0f;
    const int m0 = blockIdx.y * 128, n0 = blockIdx.x * 256;

    float acc[4][8][4];
    gemm_fp16_main(g_X, g_Wt[z], m0, n0, smem, acc);

    const int tid = threadIdx.x;
    const int warp = tid >> 5, lane = tid & 31;
    const int wm = (warp >> 2) * 64, wn = (warp & 3) * 64;
    const int gr = lane >> 2, gc = lane & 3;

#pragma unroll
    for (int mt = 0; mt < 4; mt++) {
#pragma unroll
        for (int nt = 0; nt < 8; nt++) {
            int n = n0 + wn + nt * 8 + 2 * gc;
            int h = n >> 6, d = n & 63;
            float2 bi = *(const float2*)&bias[n];
#pragma unroll
            for (int half_ = 0; half_ < 2; half_++) {
                int m = m0 + wm + mt * 16 + gr + half_ * 8;
                int bb = m >> 11, t = m & (SEQ - 1);
                float c0 = (acc[mt][nt][half_ * 2 + 0] + bi.x) * oscale;
                float c1 = (acc[mt][nt][half_ * 2 + 1] + bi.y) * oscale;
                *(__half2*)&out[(((size_t)(bb * N_HEAD + h)) * SEQ + t) * 64 + d] =
                    __floats2half2_rn(c0, c1);
            }
        }
    }
}

__global__ __launch_bounds__(256, 1) void proj_gemm_kernel(
    const float* __restrict__ bp, float* __restrict__ out)
{
    extern __shared__ __half smem[];
    const int m0 = blockIdx.y * 128, n0 = blockIdx.x * 256;

    float acc[4][8][4];
    gemm_fp16_main(g_O, g_Wt[3], m0, n0, smem, acc);

    const int tid = threadIdx.x;
    const int warp = tid >> 5, lane = tid & 31;
    const int wm = (warp >> 2) * 64, wn = (warp & 3) * 64;
    const int gr = lane >> 2, gc = lane & 3;

#pragma unroll
    for (int mt = 0; mt < 4; mt++) {
#pragma unroll
        for (int nt = 0; nt < 8; nt++) {
            int n = n0 + wn + nt * 8 + 2 * gc;
            float2 bi = *(const float2*)&bp[n];
#pragma unroll
            for (int half_ = 0; half_ < 2; half_++) {
                int m = m0 + wm + mt * 16 + gr + half_ * 8;
                float2 v = make_float2(acc[mt][nt][half_ * 2 + 0] + bi.x,
                                       acc[mt][nt][half_ * 2 + 1] + bi.y);
                *(float2*)&out[(size_t)m * N_EMBD + n] = v;
            }
        }
    }
}

// ---------------------------------------------------------------------------
// Fused causal attention: fp16 mma, ldmatrix fragments, 64-key tiles,
// cp.async double-buffered, paired q-tiles {15-px, px}. V natural layout
// with ldmatrix.trans. Strides 72 halves (conflict-free).
// ---------------------------------------------------------------------------
#define QSH 72
#define KSH 72
#define VSH 72
#define PSH 72
#define QS_H (128 * QSH)       // 9216
#define KS_H (64 * KSH)        // 4608 per buffer
#define VS_H (64 * VSH)        // 4608 per buffer
#define PS_H (128 * PSH)       // 9216
#define ATTN_SMEM_BYTES ((QS_H + 2 * KS_H + 2 * VS_H + PS_H) * 2)  // 73728

__global__ __launch_bounds__(256, 2) void attn_kernel()
{
    extern __shared__ __half sm[];
    __half* Qs  = sm;
    __half* Ks0 = Qs + QS_H;
    __half* Vs0 = Ks0 + 2 * KS_H;
    __half* Ps  = Vs0 + 2 * VS_H;
    const uint32_t sb = smem_u32(sm);

    const int px = blockIdx.x;          // 0..7
    const int h  = blockIdx.y;
    const int b  = blockIdx.z;
    const int tid  = threadIdx.x;
    const int warp = tid >> 5, lane = tid & 31;
    const int gr = lane >> 2, gc = lane & 3;
    const int rw = warp * 16;

    const __half* Kb = g_K + ((size_t)(b * N_HEAD + h)) * SEQ * 64;
    const __half* Vb = g_V + ((size_t)(b * N_HEAD + h)) * SEQ * 64;

    const int q_lane = (rw + (lane & 15)) * QSH + (lane >> 4) * 8;
    const int k_lane = ((lane >> 4) * 8 + (lane & 7)) * KSH + ((lane >> 3) & 1) * 8;
    const int p_lane = (rw + (lane & 15)) * PSH + (lane >> 4) * 8;
    const int v_lane = (lane & 15) * VSH + (lane >> 4) * 8;

    for (int pass = 0; pass < 2; pass++) {
        const int qt = pass ? px : (15 - px);
        const int q0 = qt * 128;
        const int nkt = 2 * qt + 2;     // 64-key tiles

        const __half* Qg = g_Q + (((size_t)(b * N_HEAD + h)) * SEQ + q0) * 64;

        // prologue: Q tile + KV tile 0 in one cp.async group
        {
#pragma unroll
            for (int i = 0; i < 4; i++) {
                int idx = tid + i * 256;
                int r = idx >> 3, ch = idx & 7;
                cp16(&Qs[r * QSH + ch * 8], Qg + r * 64 + ch * 8);
            }
#pragma unroll
            for (int i = 0; i < 2; i++) {
                int idx = tid + i * 256;
                int r = idx >> 3, ch = idx & 7;
                cp16(&Ks0[r * KSH + ch * 8], Kb + r * 64 + ch * 8);
                cp16(&Vs0[r * VSH + ch * 8], Vb + r * 64 + ch * 8);
            }
            CP_COMMIT();
        }

        float m_[2] = {-1e30f, -1e30f};
        float l_[2] = {0.f, 0.f};
        float o[8][4];
#pragma unroll
        for (int dt = 0; dt < 8; dt++)
#pragma unroll
            for (int j = 0; j < 4; j++) o[dt][j] = 0.f;

        const int row0 = q0 + rw + gr;
        const int row1 = row0 + 8;

        for (int kb = 0; kb < nkt; kb++) {
            __syncthreads();
            if (kb + 1 < nkt) {
                const __half* Kg = Kb + (size_t)(kb + 1) * 64 * 64;
                const __half* Vg = Vb + (size_t)(kb + 1) * 64 * 64;
                __half* Kd = Ks0 + ((kb + 1) & 1) * KS_H;
                __half* Vd = Vs0 + ((kb + 1) & 1) * VS_H;
#pragma unroll
                for (int i = 0; i < 2; i++) {
                    int idx = tid + i * 256;
                    int r = idx >> 3, ch = idx & 7;
                    cp16(&Kd[r * KSH + ch * 8], Kg + r * 64 + ch * 8);
                    cp16(&Vd[r * VSH + ch * 8], Vg + r * 64 + ch * 8);
                }
                CP_COMMIT();
                CP_WAIT(1);
            } else {
                CP_WAIT(0);
            }
            __syncthreads();

            if (kb * 64 > q0 + rw + 15) continue;   // fully masked for warp

            const uint32_t Ktb = sb + 2 * (QS_H + (kb & 1) * KS_H + k_lane);
            const uint32_t Vtb = sb + 2 * (QS_H + 2 * KS_H + (kb & 1) * VS_H + v_lane);
            const uint32_t Qsb = sb + 2 * q_lane;

            // S = Q K^T (16 x 64)
            float s[8][4];
#pragma unroll
            for (int nt = 0; nt < 8; nt++)
#pragma unroll
                for (int j = 0; j < 4; j++) s[nt][j] = 0.f;

#pragma unroll
            for (int ch = 0; ch < 4; ch++) {
                int k = ch * 16;
                unsigned af[4];
                ldm_x4(af, Qsb + 2 * k);
#pragma unroll
                for (int ntp = 0; ntp < 4; ntp++) {
                    unsigned r[4];
                    ldm_x4(r, Ktb + 2 * (ntp * 16 * KSH + k));
                    mma_fp16(s[2 * ntp], af, r);
                    mma_fp16(s[2 * ntp + 1], af, r + 2);
                }
            }

            // causal mask (Q pre-scaled; only diagonal-straddling tiles)
            if (kb * 64 + 63 > q0 + rw) {
#pragma unroll
                for (int nt = 0; nt < 8; nt++) {
                    int c0 = kb * 64 + nt * 8 + 2 * gc;
                    if (c0     > row0) s[nt][0] = -1e30f;
                    if (c0 + 1 > row0) s[nt][1] = -1e30f;
                    if (c0     > row1) s[nt][2] = -1e30f;
                    if (c0 + 1 > row1) s[nt][3] = -1e30f;
                }
            }

            // online softmax (4-lane groups own rows)
            float mx0 = -1e30f, mx1 = -1e30f;
#pragma unroll
            for (int nt = 0; nt < 8; nt++) {
                mx0 = fmaxf(mx0, fmaxf(s[nt][0], s[nt][1]));
                mx1 = fmaxf(mx1, fmaxf(s[nt][2], s[nt][3]));
            }
#pragma unroll
            for (int off = 1; off < 4; off <<= 1) {
                mx0 = fmaxf(mx0, __shfl_xor_sync(0xffffffffu, mx0, off));
                mx1 = fmaxf(mx1, __shfl_xor_sync(0xffffffffu, mx1, off));
            }
            float mn0 = fmaxf(m_[0], mx0), mn1 = fmaxf(m_[1], mx1);
            float sc0 = __expf(m_[0] - mn0), sc1 = __expf(m_[1] - mn1);
            float sum0 = 0.f, sum1 = 0.f;
#pragma unroll
            for (int nt = 0; nt < 8; nt++) {
                s[nt][0] = __expf(s[nt][0] - mn0);
                s[nt][1] = __expf(s[nt][1] - mn0);
                s[nt][2] = __expf(s[nt][2] - mn1);
                s[nt][3] = __expf(s[nt][3] - mn1);
                sum0 += s[nt][0] + s[nt][1];
                sum1 += s[nt][2] + s[nt][3];
            }
#pragma unroll
            for (int off = 1; off < 4; off <<= 1) {
                sum0 += __shfl_xor_sync(0xffffffffu, sum0, off);
                sum1 += __shfl_xor_sync(0xffffffffu, sum1, off);
            }
            l_[0] = l_[0] * sc0 + sum0;
            l_[1] = l_[1] * sc1 + sum1;
            m_[0] = mn0;
            m_[1] = mn1;
#pragma unroll
            for (int dt = 0; dt < 8; dt++) {
                o[dt][0] *= sc0; o[dt][1] *= sc0;
                o[dt][2] *= sc1; o[dt][3] *= sc1;
            }

            // publish P fp16 into warp-private Ps strip
#pragma unroll
            for (int nt = 0; nt < 8; nt++) {
                int c = nt * 8 + 2 * gc;
                *(__half2*)&Ps[(rw + gr) * PSH + c]     = __floats2half2_rn(s[nt][0], s[nt][1]);
                *(__half2*)&Ps[(rw + gr + 8) * PSH + c] = __floats2half2_rn(s[nt][2], s[nt][3]);
            }
            __syncwarp();

            // O += P @ V  (P 16x64, V 64x64 natural), ldmatrix.trans for V
            const uint32_t Psb = sb + 2 * ((QS_H + 2 * KS_H + 2 * VS_H) + p_lane);
#pragma unroll
            for (int ch = 0; ch < 4; ch++) {
                int ss = ch * 16;
                unsigned pa[4];
                ldm_x4(pa, Psb + 2 * ss);
#pragma unroll
                for (int dtp = 0; dtp < 4; dtp++) {
                    unsigned r[4];
                    ldm_x4t(r, Vtb + 2 * (ss * VSH + dtp * 16));
                    mma_fp16(o[2 * dtp], pa, r);
                    mma_fp16(o[2 * dtp + 1], pa, r + 2);
                }
            }
        }

        // normalize + store fp16 to g_O (B,T,C)
        float inv0 = 1.f / l_[0];
        float inv1 = 1.f / l_[1];
#pragma unroll
        for (int dt = 0; dt < 8; dt++) {
            int col = h * 64 + dt * 8 + 2 * gc;
            *(__half2*)&g_O[((size_t)b * SEQ + row0) * N_EMBD + col] =
                __floats2half2_rn(o[dt][0] * inv0, o[dt][1] * inv0);
            *(__half2*)&g_O[((size_t)b * SEQ + row1) * N_EMBD + col] =
                __floats2half2_rn(o[dt][2] * inv1, o[dt][3] * inv1);
        }
        __syncthreads();   // smem reuse safety before next pass
    }
}

// ---------------------------------------------------------------------------
extern "C" void kernel_launch(void* const* d_in, const int* in_sizes, int n_in,
                              void* d_out, int out_size)
{
    const float* x  = (const float*)d_in[0];
    const float* Wq = (const float*)d_in[1];
    const float* bq = (const float*)d_in[2];
    const float* Wk = (const float*)d_in[3];
    const float* bk = (const float*)d_in[4];
    const float* Wv = (const float*)d_in[5];
    const float* bv = (const float*)d_in[6];
    const float* Wp = (const float*)d_in[7];
    const float* bp = (const float*)d_in[8];
    float* out = (float*)d_out;

    cudaFuncSetAttribute(qkv_gemm_kernel,
                         cudaFuncAttributeMaxDynamicSharedMemorySize,
                         GEMM_SMEM_BYTES);
    cudaFuncSetAttribute(proj_gemm_kernel,
                         cudaFuncAttributeMaxDynamicSharedMemorySize,
                         GEMM_SMEM_BYTES);
    cudaFuncSetAttribute(attn_kernel,
                         cudaFuncAttributeMaxDynamicSharedMemorySize,
                         ATTN_SMEM_BYTES);

    prep_x_kernel<<<M_TOT * N_EMBD / 4 / 256, 256>>>(x);
    prep_w_kernel<<<dim3(32, 32, 4), dim3(32, 8)>>>(Wq, Wk, Wv, Wp);

    qkv_gemm_kernel<<<dim3(4, 64, 3), 256, GEMM_SMEM_BYTES>>>(bq, bk, bv);

    attn_kernel<<<dim3(8, N_HEAD, BATCH), 256, ATTN_SMEM_BYTES>>>();

    proj_gemm_kernel<<<dim3(4, 64, 1), 256, GEMM_SMEM_BYTES>>>(bp, out);
}

// round 10
// speedup vs baseline: 6.1153x; 1.0107x over previous
#include <cuda_runtime.h>
#include <cuda_fp16.h>
#include <math.h>
#include <stdint.h>

#define N_EMBD   1024
#define N_HEAD   16
#define HEAD_DIM 64
#define BATCH    4
#define SEQ      2048
#define M_TOT    8192

// ---------------------------------------------------------------------------
// Device scratch (fp16). Q,K,V all (B,H,T,D); O (B,T,C). Q pre-scaled 1/8.
// ---------------------------------------------------------------------------
__device__ __half g_X[(size_t)M_TOT * N_EMBD];
__device__ __half g_Wt[4][(size_t)N_EMBD * N_EMBD];   // W^T [n][k]
__device__ __half g_Q[(size_t)BATCH * N_HEAD * SEQ * HEAD_DIM];
__device__ __half g_K[(size_t)BATCH * N_HEAD * SEQ * HEAD_DIM];
__device__ __half g_V[(size_t)BATCH * N_HEAD * SEQ * HEAD_DIM];
__device__ __half g_O[(size_t)M_TOT * N_EMBD];

// ---------------------------------------------------------------------------
__device__ __forceinline__ void mma_fp16(float* d, const unsigned* a,
                                         const unsigned* b) {
    asm volatile(
        "mma.sync.aligned.m16n8k16.row.col.f32.f16.f16.f32 "
        "{%0,%1,%2,%3}, {%4,%5,%6,%7}, {%8,%9}, {%0,%1,%2,%3};"
        : "+f"(d[0]), "+f"(d[1]), "+f"(d[2]), "+f"(d[3])
        : "r"(a[0]), "r"(a[1]), "r"(a[2]), "r"(a[3]), "r"(b[0]), "r"(b[1]));
}

__device__ __forceinline__ void ldm_x4(unsigned* r, uint32_t a) {
    asm volatile("ldmatrix.sync.aligned.m8n8.x4.shared.b16 {%0,%1,%2,%3}, [%4];"
                 : "=r"(r[0]), "=r"(r[1]), "=r"(r[2]), "=r"(r[3]) : "r"(a));
}
__device__ __forceinline__ void ldm_x4t(unsigned* r, uint32_t a) {
    asm volatile("ldmatrix.sync.aligned.m8n8.x4.trans.shared.b16 {%0,%1,%2,%3}, [%4];"
                 : "=r"(r[0]), "=r"(r[1]), "=r"(r[2]), "=r"(r[3]) : "r"(a));
}

__device__ __forceinline__ void cp16(void* smem_dst, const void* gsrc) {
    unsigned u = (unsigned)__cvta_generic_to_shared(smem_dst);
    asm volatile("cp.async.cg.shared.global [%0], [%1], 16;\n"
                 :: "r"(u), "l"(gsrc));
}
#define CP_COMMIT() asm volatile("cp.async.commit_group;\n" ::: "memory")
#define CP_WAIT(N)  asm volatile("cp.async.wait_group %0;\n" :: "n"(N) : "memory")

__device__ __forceinline__ uint32_t smem_u32(const void* p) {
    return (uint32_t)__cvta_generic_to_shared(p);
}
__device__ __forceinline__ unsigned h2u(__half2 h) { return *(unsigned*)&h; }

// ---------------------------------------------------------------------------
// prep kernels
// ---------------------------------------------------------------------------
__global__ void prep_x_kernel(const float* __restrict__ x) {
    size_t i = (size_t)blockIdx.x * 256 + threadIdx.x;
    float4 v = ((const float4*)x)[i];
    uint2 u;
    u.x = h2u(__floats2half2_rn(v.x, v.y));
    u.y = h2u(__floats2half2_rn(v.z, v.w));
    ((uint2*)g_X)[i] = u;
}

__global__ void prep_w_kernel(const float* __restrict__ Wq,
                              const float* __restrict__ Wk,
                              const float* __restrict__ Wv,
                              const float* __restrict__ Wp) {
    __shared__ float tile[32][33];
    int z = blockIdx.z;
    const float* W = (z == 0) ? Wq : (z == 1) ? Wk : (z == 2) ? Wv : Wp;
    int x0 = blockIdx.x * 32;
    int y0 = blockIdx.y * 32;
    int tx = threadIdx.x;
    for (int i = threadIdx.y; i < 32; i += 8)
        tile[i][tx] = W[(size_t)(y0 + i) * N_EMBD + x0 + tx];
    __syncthreads();
    for (int i = threadIdx.y; i < 32; i += 8)
        g_Wt[z][(size_t)(x0 + i) * N_EMBD + y0 + tx] = __float2half(tile[tx][i]);
}

// ---------------------------------------------------------------------------
// fp16 GEMM (ldmatrix): block 128x256, 8 warps (2x4) of 64x64, BK=32,
// 3-stage cp.async pipeline, ONE __syncthreads per K-step.
// Stride 40 halves. smem: 3*(128+256)*40*2 = 92160 bytes.
// ---------------------------------------------------------------------------
#define GSTR 40
#define A_OFF(s) ((s) * 5120)
#define B_OFF(s) (15360 + (s) * 10240)
#define GEMM_SMEM_BYTES 92160

__device__ __forceinline__ void gemm_load_stage(
    const __half* __restrict__ A, const __half* __restrict__ Bt,
    int m0, int n0, int kb, __half* smem, int slot, int tid)
{
    const int k0 = kb * 32;
#pragma unroll
    for (int i = 0; i < 2; i++) {
        int idx = tid + i * 256;
        int r = idx >> 2, ch = idx & 3;
        cp16(smem + A_OFF(slot) + r * GSTR + ch * 8,
             A + (size_t)(m0 + r) * N_EMBD + k0 + ch * 8);
    }
#pragma unroll
    for (int i = 0; i < 4; i++) {
        int idx = tid + i * 256;
        int r = idx >> 2, ch = idx & 3;
        cp16(smem + B_OFF(slot) + r * GSTR + ch * 8,
             Bt + (size_t)(n0 + r) * N_EMBD + k0 + ch * 8);
    }
}

__device__ __forceinline__ void gemm_fp16_main(
    const __half* __restrict__ A, const __half* __restrict__ Bt,
    int m0, int n0, __half* smem, float acc[4][8][4])
{
    const int tid = threadIdx.x;
    const int warp = tid >> 5, lane = tid & 31;
    const int wm = (warp >> 2) * 64;
    const int wn = (warp & 3) * 64;
    const uint32_t sb = smem_u32(smem);
    const int a_lane = ((lane & 15) + wm) * GSTR + (lane >> 4) * 8;
    const int b_lane = ((lane >> 4) * 8 + (lane & 7) + wn) * GSTR +
                       ((lane >> 3) & 1) * 8;

#pragma unroll
    for (int mt = 0; mt < 4; mt++)
#pragma unroll
        for (int nt = 0; nt < 8; nt++)
#pragma unroll
            for (int j = 0; j < 4; j++) acc[mt][nt][j] = 0.f;

    gemm_load_stage(A, Bt, m0, n0, 0, smem, 0, tid);
    CP_COMMIT();
    gemm_load_stage(A, Bt, m0, n0, 1, smem, 1, tid);
    CP_COMMIT();

    int slot = 0, nslot = 2;
    for (int kb = 0; kb < 32; kb++) {
        if (kb + 1 < 32) { CP_WAIT(1); } else { CP_WAIT(0); }
        __syncthreads();
        if (kb + 2 < 32) {
            gemm_load_stage(A, Bt, m0, n0, kb + 2, smem, nslot, tid);
            CP_COMMIT();
        }

        const uint32_t Ab = sb + 2 * (A_OFF(slot) + a_lane);
        const uint32_t Bb = sb + 2 * (B_OFF(slot) + b_lane);
#pragma unroll
        for (int kk = 0; kk < 32; kk += 16) {
            unsigned af[4][4];
#pragma unroll
            for (int mt = 0; mt < 4; mt++)
                ldm_x4(af[mt], Ab + 2 * (mt * 16 * GSTR + kk));
            unsigned bf[8][2];
#pragma unroll
            for (int ntp = 0; ntp < 4; ntp++) {
                unsigned r[4];
                ldm_x4(r, Bb + 2 * (ntp * 16 * GSTR + kk));
                bf[2 * ntp][0] = r[0]; bf[2 * ntp][1] = r[1];
                bf[2 * ntp + 1][0] = r[2]; bf[2 * ntp + 1][1] = r[3];
            }
#pragma unroll
            for (int mt = 0; mt < 4; mt++)
#pragma unroll
                for (int nt = 0; nt < 8; nt++)
                    mma_fp16(acc[mt][nt], af[mt], bf[nt]);
        }
        slot = (slot + 1) % 3;
        nslot = (nslot + 1) % 3;
    }
}

// QKV: out (B,H,T,D) fp16, +bias; Q pre-scaled by 1/8.
__global__ __launch_bounds__(256, 1) void qkv_gemm_kernel(
    const float* __restrict__ bq, const float* __restrict__ bk,
    const float* __restrict__ bv)
{
    extern __shared__ __half smem[];
    const int z = blockIdx.z;
    const float* bias = (z == 0) ? bq : (z == 1) ? bk : bv;
    __half* out = (z == 0) ? g_Q : (z == 1) ? g_K : g_V;
    const float oscale = (z == 0) ? 0.125f : 1.0f;
    const int m0 = blockIdx.y * 128, n0 = blockIdx.x * 256;

    float acc[4][8][4];
    gemm_fp16_main(g_X, g_Wt[z], m0, n0, smem, acc);

    const int tid = threadIdx.x;
    const int warp = tid >> 5, lane = tid & 31;
    const int wm = (warp >> 2) * 64, wn = (warp & 3) * 64;
    const int gr = lane >> 2, gc = lane & 3;

#pragma unroll
    for (int mt = 0; mt < 4; mt++) {
#pragma unroll
        for (int nt = 0; nt < 8; nt++) {
            int n = n0 + wn + nt * 8 + 2 * gc;
            int h = n >> 6, d = n & 63;
            float2 bi = *(const float2*)&bias[n];
#pragma unroll
            for (int half_ = 0; half_ < 2; half_++) {
                int m = m0 + wm + mt * 16 + gr + half_ * 8;
                int bb = m >> 11, t = m & (SEQ - 1);
                float c0 = (acc[mt][nt][half_ * 2 + 0] + bi.x) * oscale;
                float c1 = (acc[mt][nt][half_ * 2 + 1] + bi.y) * oscale;
                *(__half2*)&out[(((size_t)(bb * N_HEAD + h)) * SEQ + t) * 64 + d] =
                    __floats2half2_rn(c0, c1);
            }
        }
    }
}

__global__ __launch_bounds__(256, 1) void proj_gemm_kernel(
    const float* __restrict__ bp, float* __restrict__ out)
{
    extern __shared__ __half smem[];
    const int m0 = blockIdx.y * 128, n0 = blockIdx.x * 256;

    float acc[4][8][4];
    gemm_fp16_main(g_O, g_Wt[3], m0, n0, smem, acc);

    const int tid = threadIdx.x;
    const int warp = tid >> 5, lane = tid & 31;
    const int wm = (warp >> 2) * 64, wn = (warp & 3) * 64;
    const int gr = lane >> 2, gc = lane & 3;

#pragma unroll
    for (int mt = 0; mt < 4; mt++) {
#pragma unroll
        for (int nt = 0; nt < 8; nt++) {
            int n = n0 + wn + nt * 8 + 2 * gc;
            float2 bi = *(const float2*)&bp[n];
#pragma unroll
            for (int half_ = 0; half_ < 2; half_++) {
                int m = m0 + wm + mt * 16 + gr + half_ * 8;
                float2 v = make_float2(acc[mt][nt][half_ * 2 + 0] + bi.x,
                                       acc[mt][nt][half_ * 2 + 1] + bi.y);
                *(float2*)&out[(size_t)m * N_EMBD + n] = v;
            }
        }
    }
}

// ---------------------------------------------------------------------------
// Fused causal attention: fp16 mma, 64-key tiles, cp.async double-buffered,
// paired q-tiles {15-px, px}. Q fragments AND P held in registers
// (S C-fragment == PV A-fragment layout); V natural layout via ldmatrix.trans.
// smem: Qs + 2*Ks + 2*Vs = 55296 bytes.
// ---------------------------------------------------------------------------
#define QSH 72
#define KSH 72
#define VSH 72
#define QS_H (128 * QSH)       // 9216
#define KS_H (64 * KSH)        // 4608 per buffer
#define VS_H (64 * VSH)        // 4608 per buffer
#define ATTN_SMEM_BYTES ((QS_H + 2 * KS_H + 2 * VS_H) * 2)  // 55296

__global__ __launch_bounds__(256, 2) void attn_kernel()
{
    extern __shared__ __half sm[];
    __half* Qs  = sm;
    __half* Ks0 = Qs + QS_H;
    __half* Vs0 = Ks0 + 2 * KS_H;
    const uint32_t sb = smem_u32(sm);

    const int px = blockIdx.x;          // 0..7
    const int h  = blockIdx.y;
    const int b  = blockIdx.z;
    const int tid  = threadIdx.x;
    const int warp = tid >> 5, lane = tid & 31;
    const int gr = lane >> 2, gc = lane & 3;
    const int rw = warp * 16;

    const __half* Kb = g_K + ((size_t)(b * N_HEAD + h)) * SEQ * 64;
    const __half* Vb = g_V + ((size_t)(b * N_HEAD + h)) * SEQ * 64;

    const int q_lane = (rw + (lane & 15)) * QSH + (lane >> 4) * 8;
    const int k_lane = ((lane >> 4) * 8 + (lane & 7)) * KSH + ((lane >> 3) & 1) * 8;
    const int v_lane = (lane & 15) * VSH + (lane >> 4) * 8;

    for (int pass = 0; pass < 2; pass++) {
        const int qt = pass ? px : (15 - px);
        const int q0 = qt * 128;
        const int nkt = 2 * qt + 2;     // 64-key tiles

        const __half* Qg = g_Q + (((size_t)(b * N_HEAD + h)) * SEQ + q0) * 64;

        // prologue: Q tile + KV tile 0 in one cp.async group
        {
#pragma unroll
            for (int i = 0; i < 4; i++) {
                int idx = tid + i * 256;
                int r = idx >> 3, ch = idx & 7;
                cp16(&Qs[r * QSH + ch * 8], Qg + r * 64 + ch * 8);
            }
#pragma unroll
            for (int i = 0; i < 2; i++) {
                int idx = tid + i * 256;
                int r = idx >> 3, ch = idx & 7;
                cp16(&Ks0[r * KSH + ch * 8], Kb + r * 64 + ch * 8);
                cp16(&Vs0[r * VSH + ch * 8], Vb + r * 64 + ch * 8);
            }
            CP_COMMIT();
        }

        float m_[2] = {-1e30f, -1e30f};
        float l_[2] = {0.f, 0.f};
        float o[8][4];
#pragma unroll
        for (int dt = 0; dt < 8; dt++)
#pragma unroll
            for (int j = 0; j < 4; j++) o[dt][j] = 0.f;

        unsigned qf[4][4];              // Q fragments, loaded once per pass
        const int row0 = q0 + rw + gr;
        const int row1 = row0 + 8;

        for (int kb = 0; kb < nkt; kb++) {
            __syncthreads();
            if (kb + 1 < nkt) {
                const __half* Kg = Kb + (size_t)(kb + 1) * 64 * 64;
                const __half* Vg = Vb + (size_t)(kb + 1) * 64 * 64;
                __half* Kd = Ks0 + ((kb + 1) & 1) * KS_H;
                __half* Vd = Vs0 + ((kb + 1) & 1) * VS_H;
#pragma unroll
                for (int i = 0; i < 2; i++) {
                    int idx = tid + i * 256;
                    int r = idx >> 3, ch = idx & 7;
                    cp16(&Kd[r * KSH + ch * 8], Kg + r * 64 + ch * 8);
                    cp16(&Vd[r * VSH + ch * 8], Vg + r * 64 + ch * 8);
                }
                CP_COMMIT();
                CP_WAIT(1);
            } else {
                CP_WAIT(0);
            }
            __syncthreads();

            if (kb == 0) {
                const uint32_t Qsb = sb + 2 * q_lane;
#pragma unroll
                for (int ch = 0; ch < 4; ch++)
                    ldm_x4(qf[ch], Qsb + 2 * (ch * 16));
            }

            if (kb * 64 > q0 + rw + 15) continue;   // fully masked for warp

            const uint32_t Ktb = sb + 2 * (QS_H + (kb & 1) * KS_H + k_lane);
            const uint32_t Vtb = sb + 2 * (QS_H + 2 * KS_H + (kb & 1) * VS_H + v_lane);

            // S = Q K^T (16 x 64)
            float s[8][4];
#pragma unroll
            for (int nt = 0; nt < 8; nt++)
#pragma unroll
                for (int j = 0; j < 4; j++) s[nt][j] = 0.f;

#pragma unroll
            for (int ch = 0; ch < 4; ch++) {
                int k = ch * 16;
#pragma unroll
                for (int ntp = 0; ntp < 4; ntp++) {
                    unsigned r[4];
                    ldm_x4(r, Ktb + 2 * (ntp * 16 * KSH + k));
                    mma_fp16(s[2 * ntp], qf[ch], r);
                    mma_fp16(s[2 * ntp + 1], qf[ch], r + 2);
                }
            }

            // causal mask (Q pre-scaled; only diagonal-straddling tiles)
            if (kb * 64 + 63 > q0 + rw) {
#pragma unroll
                for (int nt = 0; nt < 8; nt++) {
                    int c0 = kb * 64 + nt * 8 + 2 * gc;
                    if (c0     > row0) s[nt][0] = -1e30f;
                    if (c0 + 1 > row0) s[nt][1] = -1e30f;
                    if (c0     > row1) s[nt][2] = -1e30f;
                    if (c0 + 1 > row1) s[nt][3] = -1e30f;
                }
            }

            // online softmax (4-lane groups own rows)
            float mx0 = -1e30f, mx1 = -1e30f;
#pragma unroll
            for (int nt = 0; nt < 8; nt++) {
                mx0 = fmaxf(mx0, fmaxf(s[nt][0], s[nt][1]));
                mx1 = fmaxf(mx1, fmaxf(s[nt][2], s[nt][3]));
            }
#pragma unroll
            for (int off = 1; off < 4; off <<= 1) {
                mx0 = fmaxf(mx0, __shfl_xor_sync(0xffffffffu, mx0, off));
                mx1 = fmaxf(mx1, __shfl_xor_sync(0xffffffffu, mx1, off));
            }
            float mn0 = fmaxf(m_[0], mx0), mn1 = fmaxf(m_[1], mx1);
            float sc0 = __expf(m_[0] - mn0), sc1 = __expf(m_[1] - mn1);
            float sum0 = 0.f, sum1 = 0.f;
#pragma unroll
            for (int nt = 0; nt < 8; nt++) {
                s[nt][0] = __expf(s[nt][0] - mn0);
                s[nt][1] = __expf(s[nt][1] - mn0);
                s[nt][2] = __expf(s[nt][2] - mn1);
                s[nt][3] = __expf(s[nt][3] - mn1);
                sum0 += s[nt][0] + s[nt][1];
                sum1 += s[nt][2] + s[nt][3];
            }
#pragma unroll
            for (int off = 1; off < 4; off <<= 1) {
                sum0 += __shfl_xor_sync(0xffffffffu, sum0, off);
                sum1 += __shfl_xor_sync(0xffffffffu, sum1, off);
            }
            l_[0] = l_[0] * sc0 + sum0;
            l_[1] = l_[1] * sc1 + sum1;
            m_[0] = mn0;
            m_[1] = mn1;
#pragma unroll
            for (int dt = 0; dt < 8; dt++) {
                o[dt][0] *= sc0; o[dt][1] *= sc0;
                o[dt][2] *= sc1; o[dt][3] *= sc1;
            }

            // O += P @ V — P comes straight from S fragments (no smem).
            // S tile pair {2ch, 2ch+1} == A-fragment for key chunk ch.
#pragma unroll
            for (int ch = 0; ch < 4; ch++) {
                unsigned pa[4];
                pa[0] = h2u(__floats2half2_rn(s[2 * ch][0], s[2 * ch][1]));
                pa[1] = h2u(__floats2half2_rn(s[2 * ch][2], s[2 * ch][3]));
                pa[2] = h2u(__floats2half2_rn(s[2 * ch + 1][0], s[2 * ch + 1][1]));
                pa[3] = h2u(__floats2half2_rn(s[2 * ch + 1][2], s[2 * ch + 1][3]));
#pragma unroll
                for (int dtp = 0; dtp < 4; dtp++) {
                    unsigned r[4];
                    ldm_x4t(r, Vtb + 2 * (ch * 16 * VSH + dtp * 16));
                    mma_fp16(o[2 * dtp], pa, r);
                    mma_fp16(o[2 * dtp + 1], pa, r + 2);
                }
            }
        }

        // normalize + store fp16 to g_O (B,T,C)
        float inv0 = 1.f / l_[0];
        float inv1 = 1.f / l_[1];
#pragma unroll
        for (int dt = 0; dt < 8; dt++) {
            int col = h * 64 + dt * 8 + 2 * gc;
            *(__half2*)&g_O[((size_t)b * SEQ + row0) * N_EMBD + col] =
                __floats2half2_rn(o[dt][0] * inv0, o[dt][1] * inv0);
            *(__half2*)&g_O[((size_t)b * SEQ + row1) * N_EMBD + col] =
                __floats2half2_rn(o[dt][2] * inv1, o[dt][3] * inv1);
        }
        __syncthreads();   // smem reuse safety before next pass
    }
}

// ---------------------------------------------------------------------------
extern "C" void kernel_launch(void* const* d_in, const int* in_sizes, int n_in,
                              void* d_out, int out_size)
{
    const float* x  = (const float*)d_in[0];
    const float* Wq = (const float*)d_in[1];
    const float* bq = (const float*)d_in[2];
    const float* Wk = (const float*)d_in[3];
    const float* bk = (const float*)d_in[4];
    const float* Wv = (const float*)d_in[5];
    const float* bv = (const float*)d_in[6];
    const float* Wp = (const float*)d_in[7];
    const float* bp = (const float*)d_in[8];
    float* out = (float*)d_out;

    cudaFuncSetAttribute(qkv_gemm_kernel,
                         cudaFuncAttributeMaxDynamicSharedMemorySize,
                         GEMM_SMEM_BYTES);
    cudaFuncSetAttribute(proj_gemm_kernel,
                         cudaFuncAttributeMaxDynamicSharedMemorySize,
                         GEMM_SMEM_BYTES);
    cudaFuncSetAttribute(attn_kernel,
                         cudaFuncAttributeMaxDynamicSharedMemorySize,
                         ATTN_SMEM_BYTES);

    prep_x_kernel<<<M_TOT * N_EMBD / 4 / 256, 256>>>(x);
    prep_w_kernel<<<dim3(32, 32, 4), dim3(32, 8)>>>(Wq, Wk, Wv, Wp);

    qkv_gemm_kernel<<<dim3(4, 64, 3), 256, GEMM_SMEM_BYTES>>>(bq, bk, bv);

    attn_kernel<<<dim3(8, N_HEAD, BATCH), 256, ATTN_SMEM_BYTES>>>();

    proj_gemm_kernel<<<dim3(4, 64, 1), 256, GEMM_SMEM_BYTES>>>(bp, out);
}